// round 2
// baseline (speedup 1.0000x reference)
#include <cuda_runtime.h>
#include <cstdint>

// Problem constants: x is [NTOK, H], weights [H, H] row-major, out [NTOK, H].
// out = x @ P + 1 r^T  where
//   G = x^T x, s = x^T 1
//   M = Wk G Wv^T + (Wk s) bv^T + bk (Wv s)^T + NTOK * bk bv^T   (= k^T v)
//   P = Wq^T M / 32,  r = M^T bq / 32
static const int NTOK = 8192;
static const int HDIM = 1024;

// ---------------- scratch (no allocations allowed) ----------------
__device__ float g_part[8 * 1024 * 1024];   // split-K partials (32 MB)
__device__ float g_G[1024 * 1024];
__device__ float g_A1[1024 * 1024];
__device__ float g_M[1024 * 1024];
__device__ float g_P[1024 * 1024];
__device__ float g_spart[32 * 1024];
__device__ float g_s[1024];
__device__ float g_u[1024];
__device__ float g_w[1024];
__device__ float g_r[1024];

// ---------------- packed f32x2 helpers ----------------
#define FFMA2(d, a, b) \
    asm("fma.rn.f32x2 %0, %1, %2, %0;" : "+l"(d) : "l"(a), "l"(b))
#define PACK2(out, u32) \
    asm("mov.b64 %0, {%1, %1};" : "=l"(out) : "r"(u32))

// ---------------- generic 128x128 tiled fp32 GEMM ----------------
// C[M,N] (+optional splitK partials) = alpha * sum_k Aop[m,k]*Bop[k,n] (+ bias[n])
// AKM: A stored [K, M] (k-rows contiguous in m). else A stored [M, K].
// BKM: B stored [K, N]. else B stored [N, K].
template <bool AKM, bool BKM>
__global__ __launch_bounds__(256, 2)
void gemm128(const float* __restrict__ A, const float* __restrict__ B,
             float* __restrict__ C, int M, int N, int K,
             int lda, int ldb, int ldc, float alpha,
             const float* __restrict__ biasRow, int kPerSplit) {
    __shared__ float As[16][132];
    __shared__ float Bs[16][132];

    const int tid = threadIdx.x;
    const int tx = tid & 15;        // 0..15 -> 8 cols each
    const int ty = tid >> 4;        // 0..15 -> 8 rows each
    const int m0 = blockIdx.y * 128;
    const int n0 = blockIdx.x * 128;

    int k0 = 0, kend = K;
    float* Cp = C;
    if (gridDim.z > 1) {
        k0 = blockIdx.z * kPerSplit;
        kend = k0 + kPerSplit;
        Cp = C + (size_t)blockIdx.z * (size_t)M * (size_t)N;
    }

    unsigned long long acc[8][4];
#pragma unroll
    for (int i = 0; i < 8; i++)
#pragma unroll
        for (int j = 0; j < 4; j++) acc[i][j] = 0ULL;

    for (int kt = k0; kt < kend; kt += 16) {
        __syncthreads();
        // ---- load A tile -> As[k][m] ----
        if (AKM) {
#pragma unroll
            for (int i = 0; i < 2; i++) {
                int f = tid + i * 256;          // 512 float4
                int kr = f >> 5;                // 16 rows
                int c4 = (f & 31) * 4;          // 128 cols
                float4 v = *(const float4*)(A + (size_t)(kt + kr) * lda + m0 + c4);
                *(float4*)(&As[kr][c4]) = v;
            }
        } else {
#pragma unroll
            for (int i = 0; i < 2; i++) {
                int f = tid + i * 256;
                int mr = f >> 2;                // 128 rows
                int c4 = (f & 3) * 4;           // 16 k
                float4 v = *(const float4*)(A + (size_t)(m0 + mr) * lda + kt + c4);
                As[c4 + 0][mr] = v.x;
                As[c4 + 1][mr] = v.y;
                As[c4 + 2][mr] = v.z;
                As[c4 + 3][mr] = v.w;
            }
        }
        // ---- load B tile -> Bs[k][n] ----
        if (BKM) {
#pragma unroll
            for (int i = 0; i < 2; i++) {
                int f = tid + i * 256;
                int kr = f >> 5;
                int c4 = (f & 31) * 4;
                float4 v = *(const float4*)(B + (size_t)(kt + kr) * ldb + n0 + c4);
                *(float4*)(&Bs[kr][c4]) = v;
            }
        } else {
#pragma unroll
            for (int i = 0; i < 2; i++) {
                int f = tid + i * 256;
                int nr = f >> 2;
                int c4 = (f & 3) * 4;
                float4 v = *(const float4*)(B + (size_t)(n0 + nr) * ldb + kt + c4);
                Bs[c4 + 0][nr] = v.x;
                Bs[c4 + 1][nr] = v.y;
                Bs[c4 + 2][nr] = v.z;
                Bs[c4 + 3][nr] = v.w;
            }
        }
        __syncthreads();

#pragma unroll
        for (int kk = 0; kk < 16; kk++) {
            float4 a0 = *(const float4*)(&As[kk][ty * 8]);
            float4 a1 = *(const float4*)(&As[kk][ty * 8 + 4]);
            float a[8] = {a0.x, a0.y, a0.z, a0.w, a1.x, a1.y, a1.z, a1.w};
            unsigned long long bf[4];
#pragma unroll
            for (int j = 0; j < 4; j++)
                bf[j] = *(const unsigned long long*)(&Bs[kk][tx * 8 + j * 2]);
#pragma unroll
            for (int i = 0; i < 8; i++) {
                unsigned int au = __float_as_uint(a[i]);
                unsigned long long ap;
                PACK2(ap, au);
#pragma unroll
                for (int j = 0; j < 4; j++) FFMA2(acc[i][j], ap, bf[j]);
            }
        }
    }

    // ---- epilogue ----
#pragma unroll
    for (int i = 0; i < 8; i++) {
        int row = m0 + ty * 8 + i;
#pragma unroll
        for (int j = 0; j < 4; j++) {
            int col = n0 + tx * 8 + j * 2;
            float lo = __uint_as_float((unsigned int)(acc[i][j]));
            float hi = __uint_as_float((unsigned int)(acc[i][j] >> 32));
            lo *= alpha;
            hi *= alpha;
            if (biasRow) {
                lo += biasRow[col];
                hi += biasRow[col + 1];
            }
            *(float2*)(&Cp[(size_t)row * ldc + col]) = make_float2(lo, hi);
        }
    }
}

// ---------------- small kernels ----------------
__global__ void reduceParts(const float* __restrict__ part, float* __restrict__ C,
                            int count, int S, float alpha) {
    int i = blockIdx.x * blockDim.x + threadIdx.x;
    if (i < count) {
        float v = 0.0f;
        for (int s = 0; s < S; s++) v += part[(size_t)s * count + i];
        C[i] = v * alpha;
    }
}

// partial column sums of x: 32 row-chunks of 256
__global__ void colsum1(const float* __restrict__ x, float* __restrict__ spart) {
    int b = blockIdx.x;                 // 128 blocks
    int chunk = b >> 2;                 // 0..31
    int col = (b & 3) * 256 + threadIdx.x;
    int nStart = chunk * 256;
    float v = 0.0f;
#pragma unroll 8
    for (int n = 0; n < 256; n++) v += x[(size_t)(nStart + n) * HDIM + col];
    spart[chunk * HDIM + col] = v;
}

__global__ void colsum2(const float* __restrict__ spart, float* __restrict__ s) {
    int col = blockIdx.x * blockDim.x + threadIdx.x;
    float v = 0.0f;
#pragma unroll
    for (int c = 0; c < 32; c++) v += spart[c * HDIM + col];
    s[col] = v;
}

// out[i] = dot(W[i,:], v)   (H x H row-major W)
__global__ void matvecK(const float* __restrict__ W, const float* __restrict__ v,
                        float* __restrict__ out) {
    int gw = (blockIdx.x * blockDim.x + threadIdx.x) >> 5;
    int lane = threadIdx.x & 31;
    if (gw < HDIM) {
        const float* wrow = W + (size_t)gw * HDIM;
        float acc = 0.0f;
        for (int j = lane; j < HDIM; j += 32) acc += wrow[j] * v[j];
#pragma unroll
        for (int o = 16; o > 0; o >>= 1) acc += __shfl_xor_sync(0xFFFFFFFFu, acc, o);
        if (lane == 0) out[gw] = acc;
    }
}

// M[i,j] += u[i]*bv[j] + bk[i]*w[j] + NTOK*bk[i]*bv[j]
__global__ void mEpilogue(float* __restrict__ Mm, const float* __restrict__ u,
                          const float* __restrict__ bk, const float* __restrict__ w,
                          const float* __restrict__ bv) {
    int i = blockIdx.x;
    float ui = u[i], bki = bk[i];
    for (int j = threadIdx.x; j < HDIM; j += blockDim.x) {
        Mm[(size_t)i * HDIM + j] += ui * bv[j] + bki * w[j] + (float)NTOK * bki * bv[j];
    }
}

// r[j] = (1/32) * sum_l bq[l] * M[l, j]
__global__ void rKernel(const float* __restrict__ Mm, const float* __restrict__ bq,
                        float* __restrict__ r) {
    int j = blockIdx.x * blockDim.x + threadIdx.x;
    float acc = 0.0f;
    for (int l = 0; l < HDIM; l++) acc += bq[l] * Mm[(size_t)l * HDIM + j];
    r[j] = acc * (1.0f / 32.0f);
}

// ---------------- launch ----------------
extern "C" void kernel_launch(void* const* d_in, const int* in_sizes, int n_in,
                              void* d_out, int out_size) {
    const float* x  = (const float*)d_in[0];
    const float* Wq = (const float*)d_in[1];
    const float* bq = (const float*)d_in[2];
    const float* Wk = (const float*)d_in[3];
    const float* bk = (const float*)d_in[4];
    const float* Wv = (const float*)d_in[5];
    const float* bv = (const float*)d_in[6];
    float* out = (float*)d_out;

    float *part, *G, *A1, *Mm, *P, *spart, *s, *u, *w, *r;
    cudaGetSymbolAddress((void**)&part, g_part);
    cudaGetSymbolAddress((void**)&G, g_G);
    cudaGetSymbolAddress((void**)&A1, g_A1);
    cudaGetSymbolAddress((void**)&Mm, g_M);
    cudaGetSymbolAddress((void**)&P, g_P);
    cudaGetSymbolAddress((void**)&spart, g_spart);
    cudaGetSymbolAddress((void**)&s, g_s);
    cudaGetSymbolAddress((void**)&u, g_u);
    cudaGetSymbolAddress((void**)&w, g_w);
    cudaGetSymbolAddress((void**)&r, g_r);

    const int HH = HDIM * HDIM;
    const float inv_scale = 1.0f / 32.0f;   // 1/sqrt(1024)

    // s = x^T 1
    colsum1<<<128, 256>>>(x, spart);
    colsum2<<<4, 256>>>(spart, s);

    // G = x^T x   (split-K 8: 512 CTAs)
    gemm128<true, true><<<dim3(8, 8, 8), 256>>>(
        x, x, part, HDIM, HDIM, NTOK, HDIM, HDIM, HDIM, 1.0f, nullptr, 1024);
    reduceParts<<<(HH + 255) / 256, 256>>>(part, G, HH, 8, 1.0f);

    // u = Wk s, w = Wv s
    matvecK<<<128, 256>>>(Wk, s, u);
    matvecK<<<128, 256>>>(Wv, s, w);

    // A1 = G @ Wv^T   (split-K 4)
    gemm128<false, false><<<dim3(8, 8, 4), 256>>>(
        G, Wv, part, HDIM, HDIM, HDIM, HDIM, HDIM, HDIM, 1.0f, nullptr, 256);
    reduceParts<<<(HH + 255) / 256, 256>>>(part, A1, HH, 4, 1.0f);

    // M = Wk @ A1
    gemm128<false, true><<<dim3(8, 8, 4), 256>>>(
        Wk, A1, part, HDIM, HDIM, HDIM, HDIM, HDIM, HDIM, 1.0f, nullptr, 256);
    reduceParts<<<(HH + 255) / 256, 256>>>(part, Mm, HH, 4, 1.0f);

    // M += rank-1 bias terms
    mEpilogue<<<1024, 256>>>(Mm, u, bk, w, bv);

    // P = Wq^T @ M / 32
    gemm128<true, true><<<dim3(8, 8, 4), 256>>>(
        Wq, Mm, part, HDIM, HDIM, HDIM, HDIM, HDIM, HDIM, 1.0f, nullptr, 256);
    reduceParts<<<(HH + 255) / 256, 256>>>(part, P, HH, 4, inv_scale);

    // r = M^T bq / 32
    rKernel<<<4, 256>>>(Mm, bq, r);

    // out = x @ P + r
    gemm128<false, true><<<dim3(8, 64, 1), 256>>>(
        x, P, out, NTOK, HDIM, HDIM, HDIM, HDIM, HDIM, 1.0f, r, 1024);
}

// round 4
// speedup vs baseline: 1.9886x; 1.9886x over previous
#include <cuda_runtime.h>
#include <cuda_bf16.h>
#include <cstdint>

// out = x @ P + 1 r^T  where
//   G = x^T x (symmetric), s = x^T 1
//   M = Wk G Wv^T + (Wk s) bv^T + bk (Wv s)^T + NTOK*bk bv^T
//   P = Wq^T M / 32,  r = M^T bq / 32
// GEMM primitive (mma.sync HMMA bf16, hi/lo split x3): op(A,B)[m][n] = sum_k A[m][k]*B[n][k]
// Chain (verified):
//   G   = op(xT, xT)
//   A1t = op(Wv, G)           (G symmetric)   A1t[j][a] = A1[a][j]
//   Mt  = op(A1t, Wk)                          Mt[j][i]  = M[i][j]
//   Mt += bv u^T + w bk^T + NTOK bv bk^T ;  r = (Mt bq)/32
//   Pt  = op(Mt, WqT) = 32*P^T  (scale 1/32 at pack)
//   out = op(x, Pt') + r

static const int NTOK = 8192;
static const int HDIM = 1024;

// ---------------- device scratch (no allocations allowed) ----------------
__device__ __align__(256) __nv_bfloat16 g_xTp [2 * 1024 * 8192];  // hi plane | lo plane
__device__ __align__(256) __nv_bfloat16 g_xp  [2 * 8192 * 1024];
__device__ __align__(256) __nv_bfloat16 g_Wvp [2 * 1024 * 1024];
__device__ __align__(256) __nv_bfloat16 g_Wkp [2 * 1024 * 1024];
__device__ __align__(256) __nv_bfloat16 g_WqTp[2 * 1024 * 1024];
__device__ __align__(256) __nv_bfloat16 g_Gp  [2 * 1024 * 1024];
__device__ __align__(256) __nv_bfloat16 g_A1tp[2 * 1024 * 1024];
__device__ __align__(256) __nv_bfloat16 g_Mtp [2 * 1024 * 1024];
__device__ __align__(256) __nv_bfloat16 g_Ptp [2 * 1024 * 1024];
__device__ __align__(256) float g_part[2 * 1024 * 1024];   // split-K partials
__device__ __align__(256) float g_A1t [1024 * 1024];
__device__ __align__(256) float g_Mt  [1024 * 1024];
__device__ __align__(256) float g_Pt  [1024 * 1024];
__device__ __align__(256) float g_spart[32 * 1024];
__device__ __align__(16) float g_s[1024];
__device__ __align__(16) float g_u[1024];
__device__ __align__(16) float g_w[1024];
__device__ __align__(16) float g_r[1024];

// ---------------- helpers ----------------
__device__ __forceinline__ uint32_t smem_to_u32(const void* p) {
    uint32_t a;
    asm("{ .reg .u64 t; cvta.to.shared.u64 t, %1; cvt.u32.u64 %0, t; }"
        : "=r"(a) : "l"(p));
    return a;
}
__device__ __forceinline__ void cpAsync16(uint32_t dst, const void* src) {
    asm volatile("cp.async.cg.shared.global [%0], [%1], 16;"
                 :: "r"(dst), "l"(src) : "memory");
}
__device__ __forceinline__ void ldsm32(uint32_t& d, uint32_t addr) {
    asm volatile("ld.shared.b32 %0, [%1];" : "=r"(d) : "r"(addr));
}
__device__ __forceinline__ void mma16816(float* d, const uint32_t* a, const uint32_t* b) {
    asm volatile(
        "mma.sync.aligned.m16n8k16.row.col.f32.bf16.bf16.f32 "
        "{%0,%1,%2,%3}, {%4,%5,%6,%7}, {%8,%9}, {%0,%1,%2,%3};"
        : "+f"(d[0]), "+f"(d[1]), "+f"(d[2]), "+f"(d[3])
        : "r"(a[0]), "r"(a[1]), "r"(a[2]), "r"(a[3]), "r"(b[0]), "r"(b[1]));
}

// SMEM tile: 128 rows x 32 bf16 cols = 64B/row, 4x16B units/row.
// XOR swizzle: physical unit = c ^ ((r>>1)&3)  -> conflict-free LDS32 frag loads.
// element (tile, r, e): addr = stage + tile*8192 + r*64 + ((e>>3)^((r>>1)&3))*16 + (e&7)*2
__device__ __forceinline__ uint32_t smAddr(uint32_t st, int tile, int r, int e) {
    return st + tile * 8192 + r * 64 + ((((e >> 3) ^ ((r >> 1) & 3))) << 4) + ((e & 7) << 1);
}

#define SMEM_STAGE 32768
#define SMEM_TOTAL (2 * SMEM_STAGE)

// ---------------- pack: fp32 (+transpose / +partial-sum / *scale) -> bf16 hi/lo planes
// grid = (Kout/64, Mout/128), block 256. dst: hi plane, lo plane at +plane elems.
__global__ void packKernel(const float* __restrict__ src, int ld,
                           __nv_bfloat16* __restrict__ dst, int Ktot, size_t plane,
                           int transpose, float scale, int nPart, size_t partStride) {
    __shared__ float tile[64][129];
    const int k0 = blockIdx.x * 64, m0 = blockIdx.y * 128;
    const int tid = threadIdx.x;

    if (transpose) {
        for (int idx = tid; idx < 64 * 128; idx += 256) {
            int k = idx >> 7, m = idx & 127;
            tile[k][m] = src[(size_t)(k0 + k) * ld + m0 + m] * scale;
        }
        __syncthreads();
    }
    for (int idx = tid; idx < 128 * 16; idx += 256) {
        int m = idx >> 4, q = idx & 15;
        float v[4];
        if (transpose) {
#pragma unroll
            for (int i = 0; i < 4; i++) v[i] = tile[q * 4 + i][m];
        } else {
            const float* p = src + (size_t)(m0 + m) * ld + k0 + q * 4;
            float4 f = *(const float4*)p;
            v[0] = f.x; v[1] = f.y; v[2] = f.z; v[3] = f.w;
            for (int s = 1; s < nPart; s++) {
                float4 g2 = *(const float4*)(p + (size_t)s * partStride);
                v[0] += g2.x; v[1] += g2.y; v[2] += g2.z; v[3] += g2.w;
            }
#pragma unroll
            for (int i = 0; i < 4; i++) v[i] *= scale;
        }
        uint32_t hw[2], lw[2];
#pragma unroll
        for (int h = 0; h < 2; h++) {
            __nv_bfloat16 h0 = __float2bfloat16(v[2 * h]);
            __nv_bfloat16 h1 = __float2bfloat16(v[2 * h + 1]);
            __nv_bfloat16 l0 = __float2bfloat16(v[2 * h] - __bfloat162float(h0));
            __nv_bfloat16 l1 = __float2bfloat16(v[2 * h + 1] - __bfloat162float(h1));
            hw[h] = (uint32_t)__bfloat16_as_ushort(h0) | ((uint32_t)__bfloat16_as_ushort(h1) << 16);
            lw[h] = (uint32_t)__bfloat16_as_ushort(l0) | ((uint32_t)__bfloat16_as_ushort(l1) << 16);
        }
        size_t off = (size_t)(m0 + m) * Ktot + k0 + q * 4;
        *(uint2*)(dst + off)         = make_uint2(hw[0], hw[1]);
        *(uint2*)(dst + plane + off) = make_uint2(lw[0], lw[1]);
    }
}

// ---------------- HMMA bf16-split GEMM ----------------
// C[m][n] (+z partial) = sum_k A[m][k]*B[n][k], hi/lo 3-product emulated fp32.
// grid = (N/128, M/128, splits), block = 256 (8 warps: 2(M)x4(N), warp tile 64x32).
__global__ __launch_bounds__(256, 1)
void gemmTC(const __nv_bfloat16* __restrict__ A, const __nv_bfloat16* __restrict__ B,
            float* __restrict__ C, int ldc, int K, size_t aPlane, size_t bPlane,
            int kPerSplit, const float* __restrict__ bias, size_t partElems) {
    extern __shared__ __align__(128) uint8_t smemRaw[];
    const uint32_t sb = smem_to_u32(smemRaw);
    const int tid = threadIdx.x, wid = tid >> 5, lane = tid & 31;
    const int g = lane >> 2, t4 = lane & 3;
    const int wm = wid & 1, wn = wid >> 1;
    const int m0 = blockIdx.y * 128, n0 = blockIdx.x * 128;
    const __nv_bfloat16* Alo = A + aPlane;
    const __nv_bfloat16* Blo = B + bPlane;

    float acc[4][4][4];
#pragma unroll
    for (int i = 0; i < 4; i++)
#pragma unroll
        for (int j = 0; j < 4; j++)
#pragma unroll
            for (int k = 0; k < 4; k++) acc[i][j][k] = 0.0f;

    const int kStart = blockIdx.z * kPerSplit;

    // stage loader: 4 tiles (Ah, Al, Bh, Bl) x 512 16B-units; 8 units/thread
#define LOAD_STAGE(stageByte, kkElem)                                              \
    do {                                                                           \
        uint32_t _st = sb + (stageByte);                                           \
        int _kk = (kkElem);                                                        \
        _Pragma("unroll")                                                          \
        for (int _i = 0; _i < 8; _i++) {                                           \
            int _u = tid + (_i << 8);                                              \
            int _t = _u >> 9;                                                      \
            int _r = (_u >> 2) & 127;                                              \
            int _c = _u & 3;                                                       \
            const __nv_bfloat16* _s;                                               \
            if (_t == 0)      _s = A   + (size_t)(m0 + _r) * K + _kk + _c * 8;     \
            else if (_t == 1) _s = Alo + (size_t)(m0 + _r) * K + _kk + _c * 8;     \
            else if (_t == 2) _s = B   + (size_t)(n0 + _r) * K + _kk + _c * 8;     \
            else              _s = Blo + (size_t)(n0 + _r) * K + _kk + _c * 8;     \
            uint32_t _d = _st + _t * 8192 + _r * 64 + ((_c ^ ((_r >> 1) & 3)) << 4); \
            cpAsync16(_d, _s);                                                     \
        }                                                                          \
    } while (0)

    LOAD_STAGE(0, kStart * 32);
    asm volatile("cp.async.commit_group;" ::: "memory");

    for (int ch = 0; ch < kPerSplit; ch++) {
        if (ch + 1 < kPerSplit) {
            LOAD_STAGE(((ch + 1) & 1) * SMEM_STAGE, (kStart + ch + 1) * 32);
            asm volatile("cp.async.commit_group;" ::: "memory");
            asm volatile("cp.async.wait_group 1;" ::: "memory");
        } else {
            asm volatile("cp.async.wait_group 0;" ::: "memory");
        }
        __syncthreads();
        const uint32_t st = sb + (ch & 1) * SMEM_STAGE;

#pragma unroll
        for (int ks = 0; ks < 2; ks++) {
            const int e0 = ks * 16 + 2 * t4;
            uint32_t ah[4][4], al[4][4], bh[4][2], bl[4][2];
#pragma unroll
            for (int mt = 0; mt < 4; mt++) {
                int r1 = wm * 64 + mt * 16 + g, r2 = r1 + 8;
                ldsm32(ah[mt][0], smAddr(st, 0, r1, e0));
                ldsm32(ah[mt][1], smAddr(st, 0, r2, e0));
                ldsm32(ah[mt][2], smAddr(st, 0, r1, e0 + 8));
                ldsm32(ah[mt][3], smAddr(st, 0, r2, e0 + 8));
                ldsm32(al[mt][0], smAddr(st, 1, r1, e0));
                ldsm32(al[mt][1], smAddr(st, 1, r2, e0));
                ldsm32(al[mt][2], smAddr(st, 1, r1, e0 + 8));
                ldsm32(al[mt][3], smAddr(st, 1, r2, e0 + 8));
            }
#pragma unroll
            for (int nt = 0; nt < 4; nt++) {
                int rn = wn * 32 + nt * 8 + g;
                ldsm32(bh[nt][0], smAddr(st, 2, rn, e0));
                ldsm32(bh[nt][1], smAddr(st, 2, rn, e0 + 8));
                ldsm32(bl[nt][0], smAddr(st, 3, rn, e0));
                ldsm32(bl[nt][1], smAddr(st, 3, rn, e0 + 8));
            }
#pragma unroll
            for (int mt = 0; mt < 4; mt++)
#pragma unroll
                for (int nt = 0; nt < 4; nt++) mma16816(acc[mt][nt], ah[mt], bh[nt]);
#pragma unroll
            for (int mt = 0; mt < 4; mt++)
#pragma unroll
                for (int nt = 0; nt < 4; nt++) mma16816(acc[mt][nt], ah[mt], bl[nt]);
#pragma unroll
            for (int mt = 0; mt < 4; mt++)
#pragma unroll
                for (int nt = 0; nt < 4; nt++) mma16816(acc[mt][nt], al[mt], bh[nt]);
        }
        __syncthreads();
    }
#undef LOAD_STAGE

    // epilogue
    const int rowB = m0 + wm * 64;
    const int colB = n0 + wn * 32;
    float* Cp = C + (size_t)blockIdx.z * partElems;
#pragma unroll
    for (int nt = 0; nt < 4; nt++) {
        int c0 = colB + nt * 8 + 2 * t4;
        float b0v = 0.0f, b1v = 0.0f;
        if (bias) { b0v = bias[c0]; b1v = bias[c0 + 1]; }
#pragma unroll
        for (int mt = 0; mt < 4; mt++) {
            int r = rowB + mt * 16 + g;
            *(float2*)&Cp[(size_t)r * ldc + c0] =
                make_float2(acc[mt][nt][0] + b0v, acc[mt][nt][1] + b1v);
            *(float2*)&Cp[(size_t)(r + 8) * ldc + c0] =
                make_float2(acc[mt][nt][2] + b0v, acc[mt][nt][3] + b1v);
        }
    }
}

// ---------------- small fp32 kernels ----------------
__global__ void colsum1(const float* __restrict__ x, float* __restrict__ spart) {
    int b = blockIdx.x;
    int chunk = b >> 2;
    int col = (b & 3) * 256 + threadIdx.x;
    int nStart = chunk * 256;
    float v = 0.0f;
#pragma unroll 8
    for (int n = 0; n < 256; n++) v += x[(size_t)(nStart + n) * HDIM + col];
    spart[chunk * HDIM + col] = v;
}
__global__ void colsum2(const float* __restrict__ spart, float* __restrict__ s) {
    int col = blockIdx.x * blockDim.x + threadIdx.x;
    float v = 0.0f;
#pragma unroll
    for (int c = 0; c < 32; c++) v += spart[c * HDIM + col];
    s[col] = v;
}
__global__ void matvecK(const float* __restrict__ W, const float* __restrict__ v,
                        float* __restrict__ out, float alpha) {
    int gw = (blockIdx.x * blockDim.x + threadIdx.x) >> 5;
    int lane = threadIdx.x & 31;
    if (gw < HDIM) {
        const float* wrow = W + (size_t)gw * HDIM;
        float acc = 0.0f;
        for (int j = lane; j < HDIM; j += 32) acc += wrow[j] * v[j];
#pragma unroll
        for (int o = 16; o > 0; o >>= 1) acc += __shfl_xor_sync(0xFFFFFFFFu, acc, o);
        if (lane == 0) out[gw] = acc * alpha;
    }
}
__global__ void mEpilogueT(float* __restrict__ Mt, const float* __restrict__ u,
                           const float* __restrict__ bk, const float* __restrict__ w,
                           const float* __restrict__ bv) {
    int j = blockIdx.x;
    float bvj = bv[j], wj = w[j];
    for (int i = threadIdx.x; i < HDIM; i += blockDim.x)
        Mt[(size_t)j * HDIM + i] += bvj * u[i] + wj * bk[i] + (float)NTOK * bvj * bk[i];
}

// ---------------- launch ----------------
extern "C" void kernel_launch(void* const* d_in, const int* in_sizes, int n_in,
                              void* d_out, int out_size) {
    const float* x  = (const float*)d_in[0];
    const float* Wq = (const float*)d_in[1];
    const float* bq = (const float*)d_in[2];
    const float* Wk = (const float*)d_in[3];
    const float* bk = (const float*)d_in[4];
    const float* Wv = (const float*)d_in[5];
    const float* bv = (const float*)d_in[6];
    float* out = (float*)d_out;

    __nv_bfloat16 *xTp, *xp, *Wvp, *Wkp, *WqTp, *Gp, *A1tp, *Mtp, *Ptp;
    float *part, *A1t, *Mt, *Pt, *spart, *s, *u, *w, *r;
    cudaGetSymbolAddress((void**)&xTp, g_xTp);
    cudaGetSymbolAddress((void**)&xp, g_xp);
    cudaGetSymbolAddress((void**)&Wvp, g_Wvp);
    cudaGetSymbolAddress((void**)&Wkp, g_Wkp);
    cudaGetSymbolAddress((void**)&WqTp, g_WqTp);
    cudaGetSymbolAddress((void**)&Gp, g_Gp);
    cudaGetSymbolAddress((void**)&A1tp, g_A1tp);
    cudaGetSymbolAddress((void**)&Mtp, g_Mtp);
    cudaGetSymbolAddress((void**)&Ptp, g_Ptp);
    cudaGetSymbolAddress((void**)&part, g_part);
    cudaGetSymbolAddress((void**)&A1t, g_A1t);
    cudaGetSymbolAddress((void**)&Mt, g_Mt);
    cudaGetSymbolAddress((void**)&Pt, g_Pt);
    cudaGetSymbolAddress((void**)&spart, g_spart);
    cudaGetSymbolAddress((void**)&s, g_s);
    cudaGetSymbolAddress((void**)&u, g_u);
    cudaGetSymbolAddress((void**)&w, g_w);
    cudaGetSymbolAddress((void**)&r, g_r);

    cudaFuncSetAttribute(gemmTC, cudaFuncAttributeMaxDynamicSharedMemorySize, SMEM_TOTAL);

    const size_t PX = (size_t)1024 * 8192;   // big planes
    const size_t PH = (size_t)1024 * 1024;   // HxH planes

    // ---- packs ----
    packKernel<<<dim3(128, 8), 256>>>(x, HDIM, xTp, 8192, PX, 1, 1.0f, 1, 0);  // xT
    packKernel<<<dim3(16, 64), 256>>>(x, HDIM, xp, 1024, PX, 0, 1.0f, 1, 0);   // x
    packKernel<<<dim3(16, 8), 256>>>(Wv, HDIM, Wvp, 1024, PH, 0, 1.0f, 1, 0);
    packKernel<<<dim3(16, 8), 256>>>(Wk, HDIM, Wkp, 1024, PH, 0, 1.0f, 1, 0);
    packKernel<<<dim3(16, 8), 256>>>(Wq, HDIM, WqTp, 1024, PH, 1, 1.0f, 1, 0); // Wq^T

    // ---- s = x^T 1, u = Wk s, w = Wv s ----
    colsum1<<<128, 256>>>(x, spart);
    colsum2<<<4, 256>>>(spart, s);
    matvecK<<<128, 256>>>(Wk, s, u, 1.0f);
    matvecK<<<128, 256>>>(Wv, s, w, 1.0f);

    // ---- G = op(xT, xT)  split-K 2 (128 CTAs); pack sums partials ----
    gemmTC<<<dim3(8, 8, 2), 256, SMEM_TOTAL>>>(xTp, xTp, part, HDIM, 8192, PX, PX,
                                               128, nullptr, PH);
    packKernel<<<dim3(16, 8), 256>>>(part, HDIM, Gp, 1024, PH, 0, 1.0f, 2, PH);

    // ---- A1t = op(Wv, G) ----
    gemmTC<<<dim3(8, 8, 1), 256, SMEM_TOTAL>>>(Wvp, Gp, A1t, HDIM, 1024, PH, PH,
                                               32, nullptr, 0);
    packKernel<<<dim3(16, 8), 256>>>(A1t, HDIM, A1tp, 1024, PH, 0, 1.0f, 1, 0);

    // ---- Mt = op(A1t, Wk); rank-1 terms; r = Mt bq / 32 ----
    gemmTC<<<dim3(8, 8, 1), 256, SMEM_TOTAL>>>(A1tp, Wkp, Mt, HDIM, 1024, PH, PH,
                                               32, nullptr, 0);
    mEpilogueT<<<1024, 256>>>(Mt, u, bk, w, bv);
    matvecK<<<128, 256>>>(Mt, bq, r, 1.0f / 32.0f);
    packKernel<<<dim3(16, 8), 256>>>(Mt, HDIM, Mtp, 1024, PH, 0, 1.0f, 1, 0);

    // ---- Pt = op(Mt, WqT); scale 1/32 at pack ----
    gemmTC<<<dim3(8, 8, 1), 256, SMEM_TOTAL>>>(Mtp, WqTp, Pt, HDIM, 1024, PH, PH,
                                               32, nullptr, 0);
    packKernel<<<dim3(16, 8), 256>>>(Pt, HDIM, Ptp, 1024, PH, 0, 1.0f / 32.0f, 1, 0);

    // ---- out = op(x, Pt') + r ----
    gemmTC<<<dim3(8, 64, 1), 256, SMEM_TOTAL>>>(xp, Ptp, out, HDIM, 1024, PX, PH,
                                                32, r, 0);
}

// round 6
// speedup vs baseline: 2.3582x; 1.1858x over previous
#include <cuda_runtime.h>
#include <cuda_fp16.h>
#include <cuda_bf16.h>
#include <cstdint>

// out = x P + 1 r^T;  G = x^T x, s = x^T 1, u = Wk s, w = Wv s, w2 = w + N bv
// E = Wq^T Wk, p1 = Wq^T u, p2 = Wq^T bk
// P = (E G Wv^T + p1 bv^T + p2 w2^T)/32
// r = (Wv (G (Wk^T bq)) + (u.bq) bv + (bk.bq) w2)/32
// GEMM op(A,B)[m][n] = sum_k A[m][k]*B[n][k] via mma.sync m16n8k16:
//   G   = op(xT,xT)        fp16 2-product (A hi/lo, B hi)        [big]
//   E   = op(WqT,WkT)      bf16 3-product                        [H^3]
//   A1t = op(Wv,G)  = (G Wv^T)^T                                 [H^3]
//   Pt  = op(A1t,E) = (E A1)^T; epilogue += bv p1^T + w2 p2^T, /32 -> P^T (fp16 planes)
//   out = op(x,Pt) + r     fp16 2-product                        [big]

static const int NTOK = 8192;
static const int HDIM = 1024;
#define PX ((size_t)8192 * 1024)
#define PH ((size_t)1024 * 1024)

// ---------------- scratch ----------------
__device__ __align__(256) __half          g_xTp [2 * PX];
__device__ __align__(256) __half          g_xp  [2 * PX];
__device__ __align__(256) __nv_bfloat16   g_Wvp [2 * PH];
__device__ __align__(256) __nv_bfloat16   g_WqTp[2 * PH];
__device__ __align__(256) __nv_bfloat16   g_WkTp[2 * PH];
__device__ __align__(256) __nv_bfloat16   g_Gp  [2 * PH];
__device__ __align__(256) __nv_bfloat16   g_A1tp[2 * PH];
__device__ __align__(256) __nv_bfloat16   g_Ep  [2 * PH];
__device__ __align__(256) __half          g_Ptp [2 * PH];
__device__ __align__(256) float g_part[2 * PH];
__device__ __align__(256) float g_spart[32 * 1024];
__device__ __align__(16) float g_s[1024];
__device__ __align__(16) float g_u[1024];
__device__ __align__(16) float g_w[1024];
__device__ __align__(16) float g_z1[1024];
__device__ __align__(16) float g_z2[1024];
__device__ __align__(16) float g_p1[1024];
__device__ __align__(16) float g_p2[1024];
__device__ __align__(16) float g_r[1024];
__device__ __align__(16) float g_d[2];

// ---------------- helpers ----------------
__device__ __forceinline__ uint32_t smem_to_u32(const void* p) {
    uint32_t a;
    asm("{ .reg .u64 t; cvta.to.shared.u64 t, %1; cvt.u32.u64 %0, t; }" : "=r"(a) : "l"(p));
    return a;
}
__device__ __forceinline__ void cpAsync16(uint32_t dst, const void* src) {
    asm volatile("cp.async.cg.shared.global [%0], [%1], 16;" :: "r"(dst), "l"(src) : "memory");
}
__device__ __forceinline__ void ldsm4(uint32_t* r, uint32_t a) {
    asm volatile("ldmatrix.sync.aligned.m8n8.x4.shared.b16 {%0,%1,%2,%3}, [%4];"
                 : "=r"(r[0]), "=r"(r[1]), "=r"(r[2]), "=r"(r[3]) : "r"(a));
}
template <class CT>
__device__ __forceinline__ void mmaOp(float* d, const uint32_t* a, const uint32_t* b);
template <>
__device__ __forceinline__ void mmaOp<__half>(float* d, const uint32_t* a, const uint32_t* b) {
    asm volatile("mma.sync.aligned.m16n8k16.row.col.f32.f16.f16.f32 "
                 "{%0,%1,%2,%3}, {%4,%5,%6,%7}, {%8,%9}, {%0,%1,%2,%3};"
                 : "+f"(d[0]), "+f"(d[1]), "+f"(d[2]), "+f"(d[3])
                 : "r"(a[0]), "r"(a[1]), "r"(a[2]), "r"(a[3]), "r"(b[0]), "r"(b[1]));
}
template <>
__device__ __forceinline__ void mmaOp<__nv_bfloat16>(float* d, const uint32_t* a, const uint32_t* b) {
    asm volatile("mma.sync.aligned.m16n8k16.row.col.f32.bf16.bf16.f32 "
                 "{%0,%1,%2,%3}, {%4,%5,%6,%7}, {%8,%9}, {%0,%1,%2,%3};"
                 : "+f"(d[0]), "+f"(d[1]), "+f"(d[2]), "+f"(d[3])
                 : "r"(a[0]), "r"(a[1]), "r"(a[2]), "r"(a[3]), "r"(b[0]), "r"(b[1]));
}

#define GEMM_SMEM (3 * 24576)

// ---------------- GEMM ----------------
// CT: compute type; OT: pack-out type; NPROD: 2 (A split, B hi) / 3 (drop lo*lo)
// BN: 128 or 64; EPI: 0 fp32+bias, 1 fp32 splitK partial, 2 pack planes,
//                    3 pack planes + rank2(bv,w,p1,p2) + *1/32
template <class CT, class OT, int NPROD, int BN, int EPI>
__global__ __launch_bounds__(256, 1)
void gemmTC(const CT* __restrict__ A, const CT* __restrict__ B,
            float* __restrict__ Cf, OT* __restrict__ Ch,
            int K, size_t aPlane, size_t bPlane, int kPerSplit,
            const float* __restrict__ bias, size_t planeOrPart,
            const float* __restrict__ bvV, const float* __restrict__ wV,
            const float* __restrict__ p1V, const float* __restrict__ p2V) {
    constexpr int WNW = BN / 4;
    constexpr int NT = BN / 32;
    constexpr int STAGE = 24576;
    extern __shared__ __align__(128) uint8_t smemRaw[];
    const uint32_t sb = smem_to_u32(smemRaw);
    const int tid = threadIdx.x, wid = tid >> 5, lane = tid & 31;
    const int g = lane >> 2, t4 = lane & 3;
    const int wm = wid & 1, wn = wid >> 1;
    const int m0 = blockIdx.y * 128, n0 = blockIdx.x * BN;
    const int kStart = blockIdx.z * kPerSplit;

    float acc[4][NT][4];
#pragma unroll
    for (int i = 0; i < 4; i++)
#pragma unroll
        for (int j = 0; j < NT; j++)
#pragma unroll
            for (int k = 0; k < 4; k++) acc[i][j][k] = 0.0f;

    auto loadStage = [&](int s, int chG) {
        uint32_t st = sb + s * STAGE;
        int kk = chG * 32;
#pragma unroll
        for (int i = 0; i < 6; i++) {
            int u = tid + (i << 8);
            uint32_t d;
            const CT* src;
            if (u < 1024) {
                int t = u >> 9, r2 = (u >> 2) & 127, c = u & 3;
                src = (t ? A + aPlane : A) + (size_t)(m0 + r2) * K + kk + c * 8;
                d = st + t * 8192 + r2 * 64 + ((c ^ ((r2 >> 1) & 3)) << 4);
            } else {
                int v = u - 1024;
                if (BN == 128) {
                    int r2 = (v >> 2) & 127, c = v & 3;
                    src = B + (size_t)(n0 + r2) * K + kk + c * 8;
                    d = st + 16384 + r2 * 64 + ((c ^ ((r2 >> 1) & 3)) << 4);
                } else {
                    int t2 = v >> 8, r2 = (v >> 2) & 63, c = v & 3;
                    src = (t2 ? B + bPlane : B) + (size_t)(n0 + r2) * K + kk + c * 8;
                    d = st + 16384 + t2 * 4096 + r2 * 64 + ((c ^ ((r2 >> 1) & 3)) << 4);
                }
            }
            cpAsync16(d, src);
        }
        asm volatile("cp.async.commit_group;" ::: "memory");
    };

    loadStage(0, kStart);
    if (kPerSplit > 1) loadStage(1, kStart + 1);

    for (int ch = 0; ch < kPerSplit; ch++) {
        if (ch + 1 < kPerSplit)
            asm volatile("cp.async.wait_group 1;" ::: "memory");
        else
            asm volatile("cp.async.wait_group 0;" ::: "memory");
        __syncthreads();
        if (ch + 2 < kPerSplit) loadStage((ch + 2) % 3, kStart + ch + 2);

        const uint32_t st = sb + (ch % 3) * STAGE;
#pragma unroll
        for (int ks = 0; ks < 2; ks++) {
            uint32_t ah[4][4], al[4][4];
#pragma unroll
            for (int mt = 0; mt < 4; mt++) {
                int r2 = wm * 64 + mt * 16 + (lane & 15);
                int c = ks * 2 + (lane >> 4);
                uint32_t ad = st + r2 * 64 + ((c ^ ((r2 >> 1) & 3)) << 4);
                ldsm4(ah[mt], ad);
                ldsm4(al[mt], ad + 8192);
            }
#pragma unroll
            for (int pair = 0; pair < NT / 2; pair++) {
                int rb = wn * WNW + pair * 16 + ((lane >> 4) << 3) + (lane & 7);
                int cb = ks * 2 + ((lane >> 3) & 1);
                uint32_t bd = st + 16384 + rb * 64 + ((cb ^ ((rb >> 1) & 3)) << 4);
                uint32_t bh[4];
                ldsm4(bh, bd);
#pragma unroll
                for (int mt = 0; mt < 4; mt++) {
                    mmaOp<CT>(acc[mt][2 * pair], ah[mt], bh);
                    mmaOp<CT>(acc[mt][2 * pair + 1], ah[mt], bh + 2);
                }
#pragma unroll
                for (int mt = 0; mt < 4; mt++) {
                    mmaOp<CT>(acc[mt][2 * pair], al[mt], bh);
                    mmaOp<CT>(acc[mt][2 * pair + 1], al[mt], bh + 2);
                }
                if (NPROD == 3) {
                    uint32_t bl[4];
                    ldsm4(bl, bd + BN * 64);
#pragma unroll
                    for (int mt = 0; mt < 4; mt++) {
                        mmaOp<CT>(acc[mt][2 * pair], ah[mt], bl);
                        mmaOp<CT>(acc[mt][2 * pair + 1], ah[mt], bl + 2);
                    }
                }
            }
        }
        __syncthreads();
    }

    // ---- epilogue ----
    if (EPI <= 1) {
        float* Cp = Cf + (EPI == 1 ? (size_t)blockIdx.z * planeOrPart : 0);
#pragma unroll
        for (int nt = 0; nt < NT; nt++) {
            int c0 = n0 + wn * WNW + nt * 8 + 2 * t4;
            float b0 = 0.0f, b1 = 0.0f;
            if (EPI == 0 && bias) { b0 = bias[c0]; b1 = bias[c0 + 1]; }
#pragma unroll
            for (int mt = 0; mt < 4; mt++) {
                int r1 = m0 + wm * 64 + mt * 16 + g;
                *(float2*)&Cp[(size_t)r1 * 1024 + c0] =
                    make_float2(acc[mt][nt][0] + b0, acc[mt][nt][1] + b1);
                *(float2*)&Cp[(size_t)(r1 + 8) * 1024 + c0] =
                    make_float2(acc[mt][nt][2] + b0, acc[mt][nt][3] + b1);
            }
        }
    } else {
        const float rs = (EPI == 3) ? (1.0f / 32.0f) : 1.0f;
#pragma unroll
        for (int mt = 0; mt < 4; mt++) {
            int r1 = m0 + wm * 64 + mt * 16 + g;
            int r2 = r1 + 8;
            float bv1 = 0, w21 = 0, bv2 = 0, w22 = 0;
            if (EPI == 3) {
                bv1 = bvV[r1]; w21 = wV[r1] + 8192.0f * bv1;
                bv2 = bvV[r2]; w22 = wV[r2] + 8192.0f * bv2;
            }
#pragma unroll
            for (int nt = 0; nt < NT; nt++) {
                int c0 = n0 + wn * WNW + nt * 8 + 2 * t4;
                float pa = 0, pb = 0, qa = 0, qb = 0;
                if (EPI == 3) { pa = p1V[c0]; pb = p1V[c0 + 1]; qa = p2V[c0]; qb = p2V[c0 + 1]; }
                float v[4];
                v[0] = (acc[mt][nt][0] + bv1 * pa + w21 * qa) * rs;
                v[1] = (acc[mt][nt][1] + bv1 * pb + w21 * qb) * rs;
                v[2] = (acc[mt][nt][2] + bv2 * pa + w22 * qa) * rs;
                v[3] = (acc[mt][nt][3] + bv2 * pb + w22 * qb) * rs;
                size_t o1 = (size_t)r1 * 1024 + c0;
                size_t o2 = (size_t)r2 * 1024 + c0;
#pragma unroll
                for (int e = 0; e < 2; e++) {
                    OT h1 = OT(v[e]);
                    OT h2 = OT(v[2 + e]);
                    Ch[o1 + e] = h1;
                    Ch[o2 + e] = h2;
                    Ch[planeOrPart + o1 + e] = OT(v[e] - float(h1));
                    Ch[planeOrPart + o2 + e] = OT(v[2 + e] - float(h2));
                }
            }
        }
    }
}

// ---------------- packs ----------------
template <class T, bool TRANS>
__global__ void packH(const float* __restrict__ src, int ld, T* __restrict__ dst,
                      int Ktot, size_t plane, float scale, int nPart, size_t partStride) {
    __shared__ float tile[64][129];
    const int k0 = blockIdx.x * 64, m0 = blockIdx.y * 128;
    const int tid = threadIdx.x;
    if (TRANS) {
        for (int idx = tid; idx < 64 * 128; idx += 256) {
            int k = idx >> 7, m = idx & 127;
            tile[k][m] = src[(size_t)(k0 + k) * ld + m0 + m] * scale;
        }
        __syncthreads();
    }
    for (int idx = tid; idx < 128 * 16; idx += 256) {
        int m = idx >> 4, q = idx & 15;
        float v[4];
        if (TRANS) {
#pragma unroll
            for (int i = 0; i < 4; i++) v[i] = tile[q * 4 + i][m];
        } else {
            const float* p = src + (size_t)(m0 + m) * ld + k0 + q * 4;
            float4 f = *(const float4*)p;
            v[0] = f.x; v[1] = f.y; v[2] = f.z; v[3] = f.w;
            for (int s2 = 1; s2 < nPart; s2++) {
                float4 f2 = *(const float4*)(p + (size_t)s2 * partStride);
                v[0] += f2.x; v[1] += f2.y; v[2] += f2.z; v[3] += f2.w;
            }
#pragma unroll
            for (int i = 0; i < 4; i++) v[i] *= scale;
        }
        size_t off = (size_t)(m0 + m) * Ktot + k0 + q * 4;
#pragma unroll
        for (int i = 0; i < 4; i++) {
            T h = T(v[i]);
            dst[off + i] = h;
            dst[plane + off + i] = T(v[i] - float(h));
        }
    }
}

// fused x pack: xp[n][h] and xTp[h][n], fp16 hi/lo. grid (16, 64)
__global__ void packXfused(const float* __restrict__ x, __half* __restrict__ xp,
                           __half* __restrict__ xTp) {
    __shared__ float tile[64][132];
    const int h0 = blockIdx.x * 64, n0 = blockIdx.y * 128;
    const int tid = threadIdx.x;
    for (int idx = tid; idx < 128 * 64; idx += 256) {
        int n = idx >> 6, h = idx & 63;
        tile[h][n] = x[(size_t)(n0 + n) * HDIM + h0 + h];
    }
    __syncthreads();
    // xp rows
    for (int idx = tid; idx < 128 * 16; idx += 256) {
        int m = idx >> 4, q = idx & 15;
        size_t off = (size_t)(n0 + m) * 1024 + h0 + q * 4;
#pragma unroll
        for (int i = 0; i < 4; i++) {
            float v = tile[q * 4 + i][m];
            __half h = __float2half_rn(v);
            xp[off + i] = h;
            xp[PX + off + i] = __float2half_rn(v - __half2float(h));
        }
    }
    // xTp rows
    for (int idx = tid; idx < 64 * 32; idx += 256) {
        int h = idx >> 5, s4 = idx & 31;
        size_t off = (size_t)(h0 + h) * 8192 + n0 + s4 * 4;
#pragma unroll
        for (int i = 0; i < 4; i++) {
            float v = tile[h][s4 * 4 + i];
            __half hh = __float2half_rn(v);
            xTp[off + i] = hh;
            xTp[PX + off + i] = __float2half_rn(v - __half2float(hh));
        }
    }
}

// ---------------- vector kernels ----------------
__global__ void colsum1(const float* __restrict__ x, float* __restrict__ spart) {
    int b = blockIdx.x;
    int chunk = b >> 2;
    int col = (b & 3) * 256 + threadIdx.x;
    int nStart = chunk * 256;
    float v = 0.0f;
#pragma unroll 8
    for (int n = 0; n < 256; n++) v += x[(size_t)(nStart + n) * HDIM + col];
    spart[chunk * HDIM + col] = v;
}
__global__ void colsum2(const float* __restrict__ spart, float* __restrict__ s) {
    int col = blockIdx.x * blockDim.x + threadIdx.x;
    float v = 0.0f;
#pragma unroll
    for (int c = 0; c < 32; c++) v += spart[c * HDIM + col];
    s[col] = v;
}
// out[i] = alpha * dot(row i of W (+opt partial plane), v)
__global__ void matvecK(const float* __restrict__ W, const float* __restrict__ v,
                        float* __restrict__ out, float alpha, int nPart, size_t partStride) {
    int gw = (blockIdx.x * blockDim.x + threadIdx.x) >> 5;
    int lane = threadIdx.x & 31;
    if (gw < HDIM) {
        const float* wrow = W + (size_t)gw * HDIM;
        float acc = 0.0f;
        for (int j = lane; j < HDIM; j += 32) {
            float t = wrow[j];
            if (nPart > 1) t += wrow[partStride + j];
            acc += t * v[j];
        }
#pragma unroll
        for (int o = 16; o > 0; o >>= 1) acc += __shfl_xor_sync(0xFFFFFFFFu, acc, o);
        if (lane == 0) out[gw] = acc * alpha;
    }
}
// out[c] += sum_i W[i][c]*v[i] over row-chunk (atomic). grid (4, 8), block 256.
__global__ void matvecT(const float* __restrict__ W, const float* __restrict__ v,
                        float* __restrict__ out) {
    __shared__ float vs[128];
    int c = blockIdx.x * 256 + threadIdx.x;
    int i0 = blockIdx.y * 128;
    if (threadIdx.x < 128) vs[threadIdx.x] = v[i0 + threadIdx.x];
    __syncthreads();
    float acc = 0.0f;
#pragma unroll 8
    for (int i = 0; i < 128; i++) acc += W[(size_t)(i0 + i) * HDIM + c] * vs[i];
    atomicAdd(&out[c], acc);
}
__global__ void zeroVec(float* a, float* b, float* c) {
    int i = blockIdx.x * 256 + threadIdx.x;
    if (i < 1024) { a[i] = 0.0f; b[i] = 0.0f; c[i] = 0.0f; }
}
__global__ void dotsKernel(const float* __restrict__ u, const float* __restrict__ bq,
                           const float* __restrict__ bk, float* __restrict__ d) {
    __shared__ float s1[256], s2[256];
    int t = threadIdx.x;
    float a = 0, b = 0;
    for (int i = t; i < 1024; i += 256) { a += u[i] * bq[i]; b += bk[i] * bq[i]; }
    s1[t] = a; s2[t] = b;
    __syncthreads();
    for (int o = 128; o > 0; o >>= 1) {
        if (t < o) { s1[t] += s1[t + o]; s2[t] += s2[t + o]; }
        __syncthreads();
    }
    if (t == 0) { d[0] = s1[0]; d[1] = s2[0]; }
}
// r[j] = (dot(Wv[j,:], z2) + d0*bv[j] + d1*(w[j]+8192*bv[j]))/32
__global__ void rFinal(const float* __restrict__ Wv, const float* __restrict__ z2,
                       const float* __restrict__ d, const float* __restrict__ bv,
                       const float* __restrict__ w, float* __restrict__ r) {
    int gw = (blockIdx.x * blockDim.x + threadIdx.x) >> 5;
    int lane = threadIdx.x & 31;
    if (gw < HDIM) {
        const float* wrow = Wv + (size_t)gw * HDIM;
        float acc = 0.0f;
        for (int j = lane; j < HDIM; j += 32) acc += wrow[j] * z2[j];
#pragma unroll
        for (int o = 16; o > 0; o >>= 1) acc += __shfl_xor_sync(0xFFFFFFFFu, acc, o);
        if (lane == 0)
            r[gw] = (acc + d[0] * bv[gw] + d[1] * (w[gw] + 8192.0f * bv[gw])) * (1.0f / 32.0f);
    }
}

// ---------------- launch ----------------
extern "C" void kernel_launch(void* const* d_in, const int* in_sizes, int n_in,
                              void* d_out, int out_size) {
    const float* x  = (const float*)d_in[0];
    const float* Wq = (const float*)d_in[1];
    const float* bq = (const float*)d_in[2];
    const float* Wk = (const float*)d_in[3];
    const float* bk = (const float*)d_in[4];
    const float* Wv = (const float*)d_in[5];
    const float* bv = (const float*)d_in[6];
    float* out = (float*)d_out;

    __half *xTp, *xp, *Ptp;
    __nv_bfloat16 *Wvp, *WqTp, *WkTp, *Gp, *A1tp, *Ep;
    float *part, *spart, *s, *u, *w, *z1, *z2, *p1, *p2, *r, *d;
    cudaGetSymbolAddress((void**)&xTp, g_xTp);
    cudaGetSymbolAddress((void**)&xp, g_xp);
    cudaGetSymbolAddress((void**)&Ptp, g_Ptp);
    cudaGetSymbolAddress((void**)&Wvp, g_Wvp);
    cudaGetSymbolAddress((void**)&WqTp, g_WqTp);
    cudaGetSymbolAddress((void**)&WkTp, g_WkTp);
    cudaGetSymbolAddress((void**)&Gp, g_Gp);
    cudaGetSymbolAddress((void**)&A1tp, g_A1tp);
    cudaGetSymbolAddress((void**)&Ep, g_Ep);
    cudaGetSymbolAddress((void**)&part, g_part);
    cudaGetSymbolAddress((void**)&spart, g_spart);
    cudaGetSymbolAddress((void**)&s, g_s);
    cudaGetSymbolAddress((void**)&u, g_u);
    cudaGetSymbolAddress((void**)&w, g_w);
    cudaGetSymbolAddress((void**)&z1, g_z1);
    cudaGetSymbolAddress((void**)&z2, g_z2);
    cudaGetSymbolAddress((void**)&p1, g_p1);
    cudaGetSymbolAddress((void**)&p2, g_p2);
    cudaGetSymbolAddress((void**)&r, g_r);
    cudaGetSymbolAddress((void**)&d, g_d);

    auto GemmG   = gemmTC<__half, float, 2, 128, 1>;
    auto GemmOut = gemmTC<__half, float, 2, 128, 0>;
    auto GemmSm  = gemmTC<__nv_bfloat16, __nv_bfloat16, 3, 64, 2>;
    auto GemmPt  = gemmTC<__nv_bfloat16, __half, 3, 64, 3>;
    cudaFuncSetAttribute(GemmG, cudaFuncAttributeMaxDynamicSharedMemorySize, GEMM_SMEM);
    cudaFuncSetAttribute(GemmOut, cudaFuncAttributeMaxDynamicSharedMemorySize, GEMM_SMEM);
    cudaFuncSetAttribute(GemmSm, cudaFuncAttributeMaxDynamicSharedMemorySize, GEMM_SMEM);
    cudaFuncSetAttribute(GemmPt, cudaFuncAttributeMaxDynamicSharedMemorySize, GEMM_SMEM);

    // packs
    packXfused<<<dim3(16, 64), 256>>>(x, xp, xTp);
    packH<__nv_bfloat16, false><<<dim3(16, 8), 256>>>(Wv, HDIM, Wvp, 1024, PH, 1.0f, 1, 0);
    packH<__nv_bfloat16, true><<<dim3(16, 8), 256>>>(Wq, HDIM, WqTp, 1024, PH, 1.0f, 1, 0);
    packH<__nv_bfloat16, true><<<dim3(16, 8), 256>>>(Wk, HDIM, WkTp, 1024, PH, 1.0f, 1, 0);

    // vectors
    colsum1<<<128, 256>>>(x, spart);
    colsum2<<<4, 256>>>(spart, s);
    zeroVec<<<4, 256>>>(z1, p1, p2);
    matvecK<<<128, 256>>>(Wk, s, u, 1.0f, 1, 0);
    matvecK<<<128, 256>>>(Wv, s, w, 1.0f, 1, 0);
    matvecT<<<dim3(4, 8), 256>>>(Wk, bq, z1);
    matvecT<<<dim3(4, 8), 256>>>(Wq, bk, p2);
    matvecT<<<dim3(4, 8), 256>>>(Wq, u, p1);
    dotsKernel<<<1, 256>>>(u, bq, bk, d);

    // E = op(WqT, WkT)  -> Ep planes
    GemmSm<<<dim3(16, 8, 1), 256, GEMM_SMEM>>>(WqTp, WkTp, nullptr, Ep, 1024, PH, PH, 32,
                                               nullptr, PH, nullptr, nullptr, nullptr, nullptr);
    // G = op(xT, xT)  split-K 2 -> part
    GemmG<<<dim3(8, 8, 2), 256, GEMM_SMEM>>>(xTp, xTp, part, (float*)nullptr, 8192, PX, PX,
                                             128, nullptr, PH, nullptr, nullptr, nullptr, nullptr);
    packH<__nv_bfloat16, false><<<dim3(16, 8), 256>>>(part, HDIM, Gp, 1024, PH, 1.0f, 2, PH);
    matvecK<<<128, 256>>>(part, z1, z2, 1.0f, 2, PH);

    // A1t = op(Wv, G)
    GemmSm<<<dim3(16, 8, 1), 256, GEMM_SMEM>>>(Wvp, Gp, nullptr, A1tp, 1024, PH, PH, 32,
                                               nullptr, PH, nullptr, nullptr, nullptr, nullptr);
    // Pt = op(A1t, E) + rank2, /32  -> Ptp (fp16 planes)
    GemmPt<<<dim3(16, 8, 1), 256, GEMM_SMEM>>>(A1tp, Ep, nullptr, Ptp, 1024, PH, PH, 32,
                                               nullptr, PH, bv, w, p1, p2);
    // r
    rFinal<<<128, 256>>>(Wv, z2, d, bv, w, r);
    // out = op(x, Pt) + r
    GemmOut<<<dim3(8, 64, 1), 256, GEMM_SMEM>>>(xp, Ptp, out, (float*)nullptr, 1024, PX, PH,
                                                32, r, 0, nullptr, nullptr, nullptr, nullptr);
}

// round 8
// speedup vs baseline: 2.7709x; 1.1750x over previous
#include <cuda_runtime.h>
#include <cuda_fp16.h>
#include <cstdint>

// out = x P + 1 r^T;  G = x^T x (SYMMETRIC: triangle only), s = x^T 1,
// u = Wk s, w = Wv s, w2 = w + N bv
// E = Wq^T Wk, p1 = Wq^T u, p2 = Wq^T bk
// P = (E G Wv^T + p1 bv^T + p2 w2^T)/32
// r = (Wv (G (Wk^T bq)) + (u.bq) bv + (bk.bq) w2)/32
// GEMM op(A,B)[m][n] = sum_k A[m][k]*B[n][k], mma.sync m16n8k16 fp16:
//   G   = op(xT,xT)  2-product, upper-triangle tiles only      [big]
//   E   = op(WqT,WkT)  3-product fp16                          [H^3]
//   A1t = op(Wv,G)     3-product fp16                          [H^3]
//   Pt  = op(A1t,E) + bv p1^T + w2 p2^T, /32 -> fp16 planes    [H^3]
//   out = op(x,Pt) + r  2-product                              [big]

static const int NTOK = 8192;
static const int HDIM = 1024;
#define PX ((size_t)8192 * 1024)
#define PH ((size_t)1024 * 1024)

// ---------------- scratch ----------------
__device__ __align__(256) __half g_xTp [2 * PX];
__device__ __align__(256) __half g_xp  [2 * PX];
__device__ __align__(256) __half g_Wvp [2 * PH];
__device__ __align__(256) __half g_WqTp[2 * PH];
__device__ __align__(256) __half g_WkTp[2 * PH];
__device__ __align__(256) __half g_Gp  [2 * PH];
__device__ __align__(256) __half g_A1tp[2 * PH];
__device__ __align__(256) __half g_Ep  [2 * PH];
__device__ __align__(256) __half g_Ptp [2 * PH];
__device__ __align__(256) float g_part[4 * PH];     // split-K 4 partials (triangle valid)
__device__ __align__(256) float g_spart[32 * 1024];
__device__ __align__(16) float g_s[1024];
__device__ __align__(16) float g_u[1024];
__device__ __align__(16) float g_w[1024];
__device__ __align__(16) float g_z1[1024];
__device__ __align__(16) float g_z2[1024];
__device__ __align__(16) float g_p1[1024];
__device__ __align__(16) float g_p2[1024];
__device__ __align__(16) float g_r[1024];
__device__ __align__(16) float g_d[2];

// ---------------- helpers ----------------
__device__ __forceinline__ uint32_t smem_to_u32(const void* p) {
    uint32_t a;
    asm("{ .reg .u64 t; cvta.to.shared.u64 t, %1; cvt.u32.u64 %0, t; }" : "=r"(a) : "l"(p));
    return a;
}
__device__ __forceinline__ void cpAsync16(uint32_t dst, const void* src) {
    asm volatile("cp.async.cg.shared.global [%0], [%1], 16;" :: "r"(dst), "l"(src) : "memory");
}
__device__ __forceinline__ void ldsm4(uint32_t* r, uint32_t a) {
    asm volatile("ldmatrix.sync.aligned.m8n8.x4.shared.b16 {%0,%1,%2,%3}, [%4];"
                 : "=r"(r[0]), "=r"(r[1]), "=r"(r[2]), "=r"(r[3]) : "r"(a));
}
__device__ __forceinline__ void mmaF16(float* d, const uint32_t* a, const uint32_t* b) {
    asm volatile("mma.sync.aligned.m16n8k16.row.col.f32.f16.f16.f32 "
                 "{%0,%1,%2,%3}, {%4,%5,%6,%7}, {%8,%9}, {%0,%1,%2,%3};"
                 : "+f"(d[0]), "+f"(d[1]), "+f"(d[2]), "+f"(d[3])
                 : "r"(a[0]), "r"(a[1]), "r"(a[2]), "r"(a[3]), "r"(b[0]), "r"(b[1]));
}
// 4 floats -> hi uint2 + lo uint2 (fp16 hi/lo split), vectorized
__device__ __forceinline__ void split4(const float* v, uint2& hiw, uint2& low) {
    __half h0 = __float2half_rn(v[0]), h1 = __float2half_rn(v[1]);
    __half h2 = __float2half_rn(v[2]), h3 = __float2half_rn(v[3]);
    __half l0 = __float2half_rn(v[0] - __half2float(h0));
    __half l1 = __float2half_rn(v[1] - __half2float(h1));
    __half l2 = __float2half_rn(v[2] - __half2float(h2));
    __half l3 = __float2half_rn(v[3] - __half2float(h3));
    hiw.x = (uint32_t)__half_as_ushort(h0) | ((uint32_t)__half_as_ushort(h1) << 16);
    hiw.y = (uint32_t)__half_as_ushort(h2) | ((uint32_t)__half_as_ushort(h3) << 16);
    low.x = (uint32_t)__half_as_ushort(l0) | ((uint32_t)__half_as_ushort(l1) << 16);
    low.y = (uint32_t)__half_as_ushort(l2) | ((uint32_t)__half_as_ushort(l3) << 16);
}

#define GEMM_SMEM (3 * 24576)

// ---------------- GEMM ----------------
// NPROD: 2 = (Ahi+Alo)*Bhi ; 3 = drop lo*lo only
// BN: 128 (B hi only in smem) or 64 (B hi+lo)
// EPI: 0 fp32 out + bias row; 1 fp32 split-K partial; 2 fp16 hi/lo planes;
//      3 fp16 planes + bv p1^T + w2 p2^T, * 1/32
// SYM: gridDim.x = 36 upper-triangle tile index
template <int NPROD, int BN, int EPI, int SYM>
__global__ __launch_bounds__(256, 1)
void gemmTC(const __half* __restrict__ A, const __half* __restrict__ B,
            float* __restrict__ Cf, __half* __restrict__ Ch,
            int K, size_t aPlane, size_t bPlane, int kPerSplit,
            const float* __restrict__ bias, size_t planeOrPart,
            const float* __restrict__ bvV, const float* __restrict__ wV,
            const float* __restrict__ p1V, const float* __restrict__ p2V) {
    constexpr int WNW = BN / 4;
    constexpr int NT = BN / 32;
    constexpr int STAGE = 24576;
    extern __shared__ __align__(128) uint8_t smemRaw[];
    const uint32_t sb = smem_to_u32(smemRaw);
    const int tid = threadIdx.x, wid = tid >> 5, lane = tid & 31;
    const int g = lane >> 2, t4 = lane & 3;
    const int wm = wid & 1, wn = wid >> 1;

    int m0, n0;
    if (SYM) {
        int t = blockIdx.x, ti = 0;
        while (t >= 8 - ti) { t -= 8 - ti; ti++; }
        m0 = ti * 128;
        n0 = (ti + t) * 128;
    } else {
        m0 = blockIdx.y * 128;
        n0 = blockIdx.x * BN;
    }
    const int kStart = blockIdx.z * kPerSplit;

    float acc[4][NT][4];
#pragma unroll
    for (int i = 0; i < 4; i++)
#pragma unroll
        for (int j = 0; j < NT; j++)
#pragma unroll
            for (int k = 0; k < 4; k++) acc[i][j][k] = 0.0f;

    auto loadStage = [&](int s, int chG) {
        uint32_t st = sb + s * STAGE;
        int kk = chG * 32;
#pragma unroll
        for (int i = 0; i < 6; i++) {
            int u = tid + (i << 8);
            uint32_t d;
            const __half* src;
            if (u < 1024) {
                int t = u >> 9, r2 = (u >> 2) & 127, c = u & 3;
                src = (t ? A + aPlane : A) + (size_t)(m0 + r2) * K + kk + c * 8;
                d = st + t * 8192 + r2 * 64 + ((c ^ ((r2 >> 1) & 3)) << 4);
            } else {
                int v = u - 1024;
                if (BN == 128) {
                    int r2 = (v >> 2) & 127, c = v & 3;
                    src = B + (size_t)(n0 + r2) * K + kk + c * 8;
                    d = st + 16384 + r2 * 64 + ((c ^ ((r2 >> 1) & 3)) << 4);
                } else {
                    int t2 = v >> 8, r2 = (v >> 2) & 63, c = v & 3;
                    src = (t2 ? B + bPlane : B) + (size_t)(n0 + r2) * K + kk + c * 8;
                    d = st + 16384 + t2 * 4096 + r2 * 64 + ((c ^ ((r2 >> 1) & 3)) << 4);
                }
            }
            cpAsync16(d, src);
        }
        asm volatile("cp.async.commit_group;" ::: "memory");
    };

    loadStage(0, kStart);
    if (kPerSplit > 1) loadStage(1, kStart + 1);

    for (int ch = 0; ch < kPerSplit; ch++) {
        if (ch + 1 < kPerSplit)
            asm volatile("cp.async.wait_group 1;" ::: "memory");
        else
            asm volatile("cp.async.wait_group 0;" ::: "memory");
        __syncthreads();
        if (ch + 2 < kPerSplit) loadStage((ch + 2) % 3, kStart + ch + 2);

        const uint32_t st = sb + (ch % 3) * STAGE;
#pragma unroll
        for (int ks = 0; ks < 2; ks++) {
            uint32_t ah[4][4], al[4][4];
#pragma unroll
            for (int mt = 0; mt < 4; mt++) {
                int r2 = wm * 64 + mt * 16 + (lane & 15);
                int c = ks * 2 + (lane >> 4);
                uint32_t ad = st + r2 * 64 + ((c ^ ((r2 >> 1) & 3)) << 4);
                ldsm4(ah[mt], ad);
                ldsm4(al[mt], ad + 8192);
            }
#pragma unroll
            for (int pair = 0; pair < NT / 2; pair++) {
                int rb = wn * WNW + pair * 16 + ((lane >> 4) << 3) + (lane & 7);
                int cb = ks * 2 + ((lane >> 3) & 1);
                uint32_t bd = st + 16384 + rb * 64 + ((cb ^ ((rb >> 1) & 3)) << 4);
                uint32_t bh[4];
                ldsm4(bh, bd);
#pragma unroll
                for (int mt = 0; mt < 4; mt++) {
                    mmaF16(acc[mt][2 * pair], ah[mt], bh);
                    mmaF16(acc[mt][2 * pair + 1], ah[mt], bh + 2);
                }
#pragma unroll
                for (int mt = 0; mt < 4; mt++) {
                    mmaF16(acc[mt][2 * pair], al[mt], bh);
                    mmaF16(acc[mt][2 * pair + 1], al[mt], bh + 2);
                }
                if (NPROD == 3) {
                    uint32_t bl[4];
                    ldsm4(bl, bd + BN * 64);
#pragma unroll
                    for (int mt = 0; mt < 4; mt++) {
                        mmaF16(acc[mt][2 * pair], ah[mt], bl);
                        mmaF16(acc[mt][2 * pair + 1], ah[mt], bl + 2);
                    }
                }
            }
        }
        __syncthreads();
    }

    // ---- epilogue ----
    if (EPI <= 1) {
        float* Cp = Cf + (EPI == 1 ? (size_t)blockIdx.z * planeOrPart : 0);
#pragma unroll
        for (int nt = 0; nt < NT; nt++) {
            int c0 = n0 + wn * WNW + nt * 8 + 2 * t4;
            float b0 = 0.0f, b1 = 0.0f;
            if (EPI == 0 && bias) { b0 = bias[c0]; b1 = bias[c0 + 1]; }
#pragma unroll
            for (int mt = 0; mt < 4; mt++) {
                int r1 = m0 + wm * 64 + mt * 16 + g;
                *(float2*)&Cp[(size_t)r1 * 1024 + c0] =
                    make_float2(acc[mt][nt][0] + b0, acc[mt][nt][1] + b1);
                *(float2*)&Cp[(size_t)(r1 + 8) * 1024 + c0] =
                    make_float2(acc[mt][nt][2] + b0, acc[mt][nt][3] + b1);
            }
        }
    } else {
        const float rs = (EPI == 3) ? (1.0f / 32.0f) : 1.0f;
#pragma unroll
        for (int mt = 0; mt < 4; mt++) {
            int r1 = m0 + wm * 64 + mt * 16 + g;
            int r2 = r1 + 8;
            float bv1 = 0, w21 = 0, bv2 = 0, w22 = 0;
            if (EPI == 3) {
                bv1 = bvV[r1]; w21 = wV[r1] + 8192.0f * bv1;
                bv2 = bvV[r2]; w22 = wV[r2] + 8192.0f * bv2;
            }
#pragma unroll
            for (int nt = 0; nt < NT; nt++) {
                int c0 = n0 + wn * WNW + nt * 8 + 2 * t4;
                float pa = 0, pb = 0, qa = 0, qb = 0;
                if (EPI == 3) { pa = p1V[c0]; pb = p1V[c0 + 1]; qa = p2V[c0]; qb = p2V[c0 + 1]; }
                float v1a = (acc[mt][nt][0] + bv1 * pa + w21 * qa) * rs;
                float v1b = (acc[mt][nt][1] + bv1 * pb + w21 * qb) * rs;
                float v2a = (acc[mt][nt][2] + bv2 * pa + w22 * qa) * rs;
                float v2b = (acc[mt][nt][3] + bv2 * pb + w22 * qb) * rs;
                size_t o1 = (size_t)r1 * 1024 + c0;
                size_t o2 = (size_t)r2 * 1024 + c0;
                __half h;
                h = __float2half_rn(v1a); Ch[o1] = h;
                Ch[planeOrPart + o1] = __float2half_rn(v1a - __half2float(h));
                h = __float2half_rn(v1b); Ch[o1 + 1] = h;
                Ch[planeOrPart + o1 + 1] = __float2half_rn(v1b - __half2float(h));
                h = __float2half_rn(v2a); Ch[o2] = h;
                Ch[planeOrPart + o2] = __float2half_rn(v2a - __half2float(h));
                h = __float2half_rn(v2b); Ch[o2 + 1] = h;
                Ch[planeOrPart + o2 + 1] = __float2half_rn(v2b - __half2float(h));
            }
        }
    }
}

// ---------------- packs ----------------
template <bool TRANS>
__global__ void packH(const float* __restrict__ src, int ld, __half* __restrict__ dst,
                      int Ktot, size_t plane) {
    __shared__ float tile[64][129];
    const int k0 = blockIdx.x * 64, m0 = blockIdx.y * 128;
    const int tid = threadIdx.x;
    if (TRANS) {
        for (int idx = tid; idx < 64 * 128; idx += 256) {
            int k = idx >> 7, m = idx & 127;
            tile[k][m] = src[(size_t)(k0 + k) * ld + m0 + m];
        }
        __syncthreads();
    }
    for (int idx = tid; idx < 128 * 16; idx += 256) {
        int m = idx >> 4, q = idx & 15;
        float v[4];
        if (TRANS) {
#pragma unroll
            for (int i = 0; i < 4; i++) v[i] = tile[q * 4 + i][m];
        } else {
            float4 f = *(const float4*)(src + (size_t)(m0 + m) * ld + k0 + q * 4);
            v[0] = f.x; v[1] = f.y; v[2] = f.z; v[3] = f.w;
        }
        uint2 hiw, low;
        split4(v, hiw, low);
        size_t off = (size_t)(m0 + m) * Ktot + k0 + q * 4;
        *(uint2*)(dst + off) = hiw;
        *(uint2*)(dst + plane + off) = low;
    }
}

// fused x pack: xp[n][h] and xTp[h][n], fp16 hi/lo planes. grid (16, 64)
__global__ void packXfused(const float* __restrict__ x, __half* __restrict__ xp,
                           __half* __restrict__ xTp) {
    __shared__ float tile[64][132];
    const int h0 = blockIdx.x * 64, n0 = blockIdx.y * 128;
    const int tid = threadIdx.x;
    for (int idx = tid; idx < 128 * 64; idx += 256) {
        int n = idx >> 6, h = idx & 63;
        tile[h][n] = x[(size_t)(n0 + n) * HDIM + h0 + h];
    }
    __syncthreads();
    for (int idx = tid; idx < 128 * 16; idx += 256) {
        int m = idx >> 4, q = idx & 15;
        float v[4];
#pragma unroll
        for (int i = 0; i < 4; i++) v[i] = tile[q * 4 + i][m];
        uint2 hiw, low;
        split4(v, hiw, low);
        size_t off = (size_t)(n0 + m) * 1024 + h0 + q * 4;
        *(uint2*)(xp + off) = hiw;
        *(uint2*)(xp + PX + off) = low;
    }
    for (int idx = tid; idx < 64 * 32; idx += 256) {
        int h = idx >> 5, s4 = idx & 31;
        float v[4];
#pragma unroll
        for (int i = 0; i < 4; i++) v[i] = tile[h][s4 * 4 + i];
        uint2 hiw, low;
        split4(v, hiw, low);
        size_t off = (size_t)(h0 + h) * 8192 + n0 + s4 * 4;
        *(uint2*)(xTp + off) = hiw;
        *(uint2*)(xTp + PX + off) = low;
    }
}

// G pack with symmetric mirror: Gp[m][k] = sum_z part_z[m][k] if mtile<=ktile
//                               else sum_z part_z[k][m].  grid (16, 8)
__global__ void packG(const float* __restrict__ part, __half* __restrict__ dst) {
    __shared__ float tile[64][129];
    const int k0 = blockIdx.x * 64, m0 = blockIdx.y * 128;
    const int mt = m0 >> 7, kt = k0 >> 7;
    const int tid = threadIdx.x;
    const bool mirror = (mt > kt);
    if (mirror) {
        for (int idx = tid; idx < 64 * 128; idx += 256) {
            int k = idx >> 7, m = idx & 127;
            const float* p = part + (size_t)(k0 + k) * 1024 + m0 + m;
            tile[k][m] = p[0] + p[PH] + p[2 * PH] + p[3 * PH];
        }
        __syncthreads();
    }
    for (int idx = tid; idx < 128 * 16; idx += 256) {
        int m = idx >> 4, q = idx & 15;
        float v[4];
        if (mirror) {
#pragma unroll
            for (int i = 0; i < 4; i++) v[i] = tile[q * 4 + i][m];
        } else {
            const float* p = part + (size_t)(m0 + m) * 1024 + k0 + q * 4;
            float4 a = *(const float4*)p;
            float4 b = *(const float4*)(p + PH);
            float4 c = *(const float4*)(p + 2 * PH);
            float4 e = *(const float4*)(p + 3 * PH);
            v[0] = a.x + b.x + c.x + e.x;
            v[1] = a.y + b.y + c.y + e.y;
            v[2] = a.z + b.z + c.z + e.z;
            v[3] = a.w + b.w + c.w + e.w;
        }
        uint2 hiw, low;
        split4(v, hiw, low);
        size_t off = (size_t)(m0 + m) * 1024 + k0 + q * 4;
        *(uint2*)(dst + off) = hiw;
        *(uint2*)(dst + PH + off) = low;
    }
}

// ---------------- vector kernels ----------------
__global__ void colsum1(const float* __restrict__ x, float* __restrict__ spart) {
    int b = blockIdx.x;
    int chunk = b >> 2;
    int col = (b & 3) * 256 + threadIdx.x;
    int nStart = chunk * 256;
    float v = 0.0f;
#pragma unroll 8
    for (int n = 0; n < 256; n++) v += x[(size_t)(nStart + n) * HDIM + col];
    spart[chunk * HDIM + col] = v;
}
__global__ void colsum2(const float* __restrict__ spart, float* __restrict__ s) {
    int col = blockIdx.x * blockDim.x + threadIdx.x;
    float v = 0.0f;
#pragma unroll
    for (int c = 0; c < 32; c++) v += spart[c * HDIM + col];
    s[col] = v;
}
__global__ void matvecK(const float* __restrict__ W, const float* __restrict__ v,
                        float* __restrict__ out, float alpha) {
    int gw = (blockIdx.x * blockDim.x + threadIdx.x) >> 5;
    int lane = threadIdx.x & 31;
    if (gw < HDIM) {
        const float* wrow = W + (size_t)gw * HDIM;
        float acc = 0.0f;
        for (int j = lane; j < HDIM; j += 32) acc += wrow[j] * v[j];
#pragma unroll
        for (int o = 16; o > 0; o >>= 1) acc += __shfl_xor_sync(0xFFFFFFFFu, acc, o);
        if (lane == 0) out[gw] = acc * alpha;
    }
}
// z2[i] = dot(G[i,:], z1) using fp16 hi+lo planes
__global__ void matvecH(const __half* __restrict__ Gp, const float* __restrict__ z1,
                        float* __restrict__ z2) {
    int gw = (blockIdx.x * blockDim.x + threadIdx.x) >> 5;
    int lane = threadIdx.x & 31;
    if (gw < HDIM) {
        const __half* row = Gp + (size_t)gw * 1024;
        float acc = 0.0f;
        for (int j = lane; j < HDIM; j += 32)
            acc += (__half2float(row[j]) + __half2float(row[PH + j])) * z1[j];
#pragma unroll
        for (int o = 16; o > 0; o >>= 1) acc += __shfl_xor_sync(0xFFFFFFFFu, acc, o);
        if (lane == 0) z2[gw] = acc;
    }
}
__global__ void matvecT(const float* __restrict__ W, const float* __restrict__ v,
                        float* __restrict__ out) {
    __shared__ float vs[128];
    int c = blockIdx.x * 256 + threadIdx.x;
    int i0 = blockIdx.y * 128;
    if (threadIdx.x < 128) vs[threadIdx.x] = v[i0 + threadIdx.x];
    __syncthreads();
    float acc = 0.0f;
#pragma unroll 8
    for (int i = 0; i < 128; i++) acc += W[(size_t)(i0 + i) * HDIM + c] * vs[i];
    atomicAdd(&out[c], acc);
}
__global__ void zeroVec(float* a, float* b, float* c) {
    int i = blockIdx.x * 256 + threadIdx.x;
    if (i < 1024) { a[i] = 0.0f; b[i] = 0.0f; c[i] = 0.0f; }
}
__global__ void dotsKernel(const float* __restrict__ u, const float* __restrict__ bq,
                           const float* __restrict__ bk, float* __restrict__ d) {
    __shared__ float s1[256], s2[256];
    int t = threadIdx.x;
    float a = 0, b = 0;
    for (int i = t; i < 1024; i += 256) { a += u[i] * bq[i]; b += bk[i] * bq[i]; }
    s1[t] = a; s2[t] = b;
    __syncthreads();
    for (int o = 128; o > 0; o >>= 1) {
        if (t < o) { s1[t] += s1[t + o]; s2[t] += s2[t + o]; }
        __syncthreads();
    }
    if (t == 0) { d[0] = s1[0]; d[1] = s2[0]; }
}
__global__ void rFinal(const float* __restrict__ Wv, const float* __restrict__ z2,
                       const float* __restrict__ d, const float* __restrict__ bv,
                       const float* __restrict__ w, float* __restrict__ r) {
    int gw = (blockIdx.x * blockDim.x + threadIdx.x) >> 5;
    int lane = threadIdx.x & 31;
    if (gw < HDIM) {
        const float* wrow = Wv + (size_t)gw * HDIM;
        float acc = 0.0f;
        for (int j = lane; j < HDIM; j += 32) acc += wrow[j] * z2[j];
#pragma unroll
        for (int o = 16; o > 0; o >>= 1) acc += __shfl_xor_sync(0xFFFFFFFFu, acc, o);
        if (lane == 0)
            r[gw] = (acc + d[0] * bv[gw] + d[1] * (w[gw] + 8192.0f * bv[gw])) * (1.0f / 32.0f);
    }
}

// ---------------- launch ----------------
extern "C" void kernel_launch(void* const* d_in, const int* in_sizes, int n_in,
                              void* d_out, int out_size) {
    const float* x  = (const float*)d_in[0];
    const float* Wq = (const float*)d_in[1];
    const float* bq = (const float*)d_in[2];
    const float* Wk = (const float*)d_in[3];
    const float* bk = (const float*)d_in[4];
    const float* Wv = (const float*)d_in[5];
    const float* bv = (const float*)d_in[6];
    float* out = (float*)d_out;

    __half *xTp, *xp, *Ptp, *Wvp, *WqTp, *WkTp, *Gp, *A1tp, *Ep;
    float *part, *spart, *s, *u, *w, *z1, *z2, *p1, *p2, *r, *d;
    cudaGetSymbolAddress((void**)&xTp, g_xTp);
    cudaGetSymbolAddress((void**)&xp, g_xp);
    cudaGetSymbolAddress((void**)&Ptp, g_Ptp);
    cudaGetSymbolAddress((void**)&Wvp, g_Wvp);
    cudaGetSymbolAddress((void**)&WqTp, g_WqTp);
    cudaGetSymbolAddress((void**)&WkTp, g_WkTp);
    cudaGetSymbolAddress((void**)&Gp, g_Gp);
    cudaGetSymbolAddress((void**)&A1tp, g_A1tp);
    cudaGetSymbolAddress((void**)&Ep, g_Ep);
    cudaGetSymbolAddress((void**)&part, g_part);
    cudaGetSymbolAddress((void**)&spart, g_spart);
    cudaGetSymbolAddress((void**)&s, g_s);
    cudaGetSymbolAddress((void**)&u, g_u);
    cudaGetSymbolAddress((void**)&w, g_w);
    cudaGetSymbolAddress((void**)&z1, g_z1);
    cudaGetSymbolAddress((void**)&z2, g_z2);
    cudaGetSymbolAddress((void**)&p1, g_p1);
    cudaGetSymbolAddress((void**)&p2, g_p2);
    cudaGetSymbolAddress((void**)&r, g_r);
    cudaGetSymbolAddress((void**)&d, g_d);

    auto GemmG   = gemmTC<2, 128, 1, 1>;   // symmetric triangle, split-K partials
    auto GemmOut = gemmTC<2, 128, 0, 0>;   // fp32 + bias row
    auto GemmSm  = gemmTC<3, 64, 2, 0>;    // fp16 planes out
    auto GemmPt  = gemmTC<3, 64, 3, 0>;    // fp16 planes + rank-2 + 1/32
    cudaFuncSetAttribute(GemmG, cudaFuncAttributeMaxDynamicSharedMemorySize, GEMM_SMEM);
    cudaFuncSetAttribute(GemmOut, cudaFuncAttributeMaxDynamicSharedMemorySize, GEMM_SMEM);
    cudaFuncSetAttribute(GemmSm, cudaFuncAttributeMaxDynamicSharedMemorySize, GEMM_SMEM);
    cudaFuncSetAttribute(GemmPt, cudaFuncAttributeMaxDynamicSharedMemorySize, GEMM_SMEM);

    // packs
    packXfused<<<dim3(16, 64), 256>>>(x, xp, xTp);
    packH<false><<<dim3(16, 8), 256>>>(Wv, HDIM, Wvp, 1024, PH);
    packH<true><<<dim3(16, 8), 256>>>(Wq, HDIM, WqTp, 1024, PH);
    packH<true><<<dim3(16, 8), 256>>>(Wk, HDIM, WkTp, 1024, PH);

    // vectors
    colsum1<<<128, 256>>>(x, spart);
    colsum2<<<4, 256>>>(spart, s);
    zeroVec<<<4, 256>>>(z1, p1, p2);
    matvecK<<<128, 256>>>(Wk, s, u, 1.0f);
    matvecK<<<128, 256>>>(Wv, s, w, 1.0f);
    matvecT<<<dim3(4, 8), 256>>>(Wk, bq, z1);
    matvecT<<<dim3(4, 8), 256>>>(Wq, bk, p2);
    matvecT<<<dim3(4, 8), 256>>>(Wq, u, p1);
    dotsKernel<<<1, 256>>>(u, bq, bk, d);

    // E = op(WqT, WkT)
    GemmSm<<<dim3(16, 8, 1), 256, GEMM_SMEM>>>(WqTp, WkTp, nullptr, Ep, 1024, PH, PH, 32,
                                               nullptr, PH, nullptr, nullptr, nullptr, nullptr);
    // G = op(xT, xT): 36 triangle tiles x split-K 4 = 144 CTAs
    GemmG<<<dim3(36, 1, 4), 256, GEMM_SMEM>>>(xTp, xTp, part, nullptr, 8192, PX, PX,
                                              64, nullptr, PH, nullptr, nullptr, nullptr, nullptr);
    packG<<<dim3(16, 8), 256>>>(part, Gp);
    matvecH<<<128, 256>>>(Gp, z1, z2);

    // A1t = op(Wv, G)
    GemmSm<<<dim3(16, 8, 1), 256, GEMM_SMEM>>>(Wvp, Gp, nullptr, A1tp, 1024, PH, PH, 32,
                                               nullptr, PH, nullptr, nullptr, nullptr, nullptr);
    // Pt = op(A1t, E) + rank2, /32
    GemmPt<<<dim3(16, 8, 1), 256, GEMM_SMEM>>>(A1tp, Ep, nullptr, Ptp, 1024, PH, PH, 32,
                                               nullptr, PH, bv, w, p1, p2);
    // r
    rFinal<<<128, 256>>>(Wv, z2, d, bv, w, r);
    // out = op(x, Pt) + r
    GemmOut<<<dim3(8, 64, 1), 256, GEMM_SMEM>>>(xp, Ptp, out, nullptr, 1024, PX, PH,
                                                32, r, 0, nullptr, nullptr, nullptr, nullptr);
}

// round 16
// speedup vs baseline: 3.5501x; 1.2812x over previous
#include <cuda_runtime.h>
#include <cuda_fp16.h>
#include <cstdint>

// out = x P + 1 r^T;  G = x^T x (SYMMETRIC triangle), s = x^T 1,
// u = Wk s, w = Wv s, w2 = w + N bv
// E = Wq^T Wk, p1 = Wq^T u, p2 = Wq^T bk
// P = (E G Wv^T + p1 bv^T + p2 w2^T)/32
// r = (Wv (G (Wk^T bq)) + (u.bq) bv + (bk.bq) w2)/32
// mma.sync m16n8k16 fp16 GEMMs:
//   G   = op(xT,xT)   2-product, triangle tiles      [big]
//   E   = op(WqT,WkT) 3-product                      [H^3]
//   A1t = op(Wv,G)    3-product                      [H^3]
//   Pt  = op(A1t,E) + rank2, /32                     [H^3]
//   out = op(x,Pt) + r   1-product (hi*hi)           [big]

static const int NTOK = 8192;
static const int HDIM = 1024;
#define PX ((size_t)8192 * 1024)
#define PH ((size_t)1024 * 1024)

// ---------------- scratch ----------------
__device__ __align__(256) __half g_xTp [2 * PX];
__device__ __align__(256) __half g_xp  [2 * PX];
__device__ __align__(256) __half g_Wvp [2 * PH];
__device__ __align__(256) __half g_WqTp[2 * PH];
__device__ __align__(256) __half g_WkTp[2 * PH];
__device__ __align__(256) __half g_Gp  [2 * PH];
__device__ __align__(256) __half g_A1tp[2 * PH];
__device__ __align__(256) __half g_Ep  [2 * PH];
__device__ __align__(256) __half g_Ptp [2 * PH];
__device__ __align__(256) float g_part[4 * PH];
__device__ __align__(16) float g_s[1024];
__device__ __align__(16) float g_u[1024];
__device__ __align__(16) float g_w[1024];
__device__ __align__(16) float g_z1[1024];
__device__ __align__(16) float g_z2[1024];
__device__ __align__(16) float g_p1[1024];
__device__ __align__(16) float g_p2[1024];
__device__ __align__(16) float g_r[1024];
__device__ __align__(16) float g_d[2];

// ---------------- helpers ----------------
__device__ __forceinline__ uint32_t smem_to_u32(const void* p) {
    uint32_t a;
    asm("{ .reg .u64 t; cvta.to.shared.u64 t, %1; cvt.u32.u64 %0, t; }" : "=r"(a) : "l"(p));
    return a;
}
__device__ __forceinline__ void cpAsync16(uint32_t dst, const void* src) {
    asm volatile("cp.async.cg.shared.global [%0], [%1], 16;" :: "r"(dst), "l"(src) : "memory");
}
__device__ __forceinline__ void ldsm4(uint32_t* r, uint32_t a) {
    asm volatile("ldmatrix.sync.aligned.m8n8.x4.shared.b16 {%0,%1,%2,%3}, [%4];"
                 : "=r"(r[0]), "=r"(r[1]), "=r"(r[2]), "=r"(r[3]) : "r"(a));
}
__device__ __forceinline__ void mmaF16(float* d, const uint32_t* a, const uint32_t* b) {
    asm volatile("mma.sync.aligned.m16n8k16.row.col.f32.f16.f16.f32 "
                 "{%0,%1,%2,%3}, {%4,%5,%6,%7}, {%8,%9}, {%0,%1,%2,%3};"
                 : "+f"(d[0]), "+f"(d[1]), "+f"(d[2]), "+f"(d[3])
                 : "r"(a[0]), "r"(a[1]), "r"(a[2]), "r"(a[3]), "r"(b[0]), "r"(b[1]));
}
__device__ __forceinline__ void split4(const float* v, uint2& hiw, uint2& low) {
    __half h0 = __float2half_rn(v[0]), h1 = __float2half_rn(v[1]);
    __half h2 = __float2half_rn(v[2]), h3 = __float2half_rn(v[3]);
    __half l0 = __float2half_rn(v[0] - __half2float(h0));
    __half l1 = __float2half_rn(v[1] - __half2float(h1));
    __half l2 = __float2half_rn(v[2] - __half2float(h2));
    __half l3 = __float2half_rn(v[3] - __half2float(h3));
    hiw.x = (uint32_t)__half_as_ushort(h0) | ((uint32_t)__half_as_ushort(h1) << 16);
    hiw.y = (uint32_t)__half_as_ushort(h2) | ((uint32_t)__half_as_ushort(h3) << 16);
    low.x = (uint32_t)__half_as_ushort(l0) | ((uint32_t)__half_as_ushort(l1) << 16);
    low.y = (uint32_t)__half_as_ushort(l2) | ((uint32_t)__half_as_ushort(l3) << 16);
}

#define GEMM_SMEM (3 * 24576)

// ---------------- GEMM ----------------
// NPROD: 1 = Ahi*Bhi; 2 = (Ahi+Alo)*Bhi; 3 = drop lo*lo only
// BN: 128 (B hi only) or 64 (B hi+lo)
// EPI: 0 fp32 + bias row; 1 fp32 split-K partial; 2 fp16 hi/lo planes;
//      3 fp16 planes + bv p1^T + w2 p2^T, * 1/32
// SYM: gridDim.x = 36 upper-triangle tile index
template <int NPROD, int BN, int EPI, int SYM>
__global__ __launch_bounds__(256, 1)
void gemmTC(const __half* __restrict__ A, const __half* __restrict__ B,
            float* __restrict__ Cf, __half* __restrict__ Ch,
            int K, size_t aPlane, size_t bPlane, int kPerSplit,
            const float* __restrict__ bias, size_t planeOrPart,
            const float* __restrict__ bvV, const float* __restrict__ wV,
            const float* __restrict__ p1V, const float* __restrict__ p2V) {
    constexpr int WNW = BN / 4;
    constexpr int NT = BN / 32;
    constexpr int STAGE = 24576;
    constexpr int APL = (NPROD >= 2) ? 2 : 1;          // A planes in smem
    constexpr int BPL = (NPROD == 3) ? 2 : 1;          // B planes in smem
    constexpr uint32_t BBASE = APL * 8192;
    extern __shared__ __align__(128) uint8_t smemRaw[];
    const uint32_t sb = smem_to_u32(smemRaw);
    const int tid = threadIdx.x, wid = tid >> 5, lane = tid & 31;
    const int g = lane >> 2, t4 = lane & 3;
    const int wm = wid & 1, wn = wid >> 1;

    int m0, n0;
    if (SYM) {
        int t = blockIdx.x, ti = 0;
        while (t >= 8 - ti) { t -= 8 - ti; ti++; }
        m0 = ti * 128;
        n0 = (ti + t) * 128;
    } else {
        m0 = blockIdx.y * 128;
        n0 = blockIdx.x * BN;
    }
    const int kStart = blockIdx.z * kPerSplit;

    float acc[4][NT][4];
#pragma unroll
    for (int i = 0; i < 4; i++)
#pragma unroll
        for (int j = 0; j < NT; j++)
#pragma unroll
            for (int k = 0; k < 4; k++) acc[i][j][k] = 0.0f;

    auto loadStage = [&](int s, int chG) {
        uint32_t st = sb + s * STAGE;
        int kk = chG * 32;
        constexpr int AUNITS = 512 * APL;
        constexpr int BUNITS = BN * 4 * BPL;
        constexpr int ITERS = (AUNITS + BUNITS) / 256;
#pragma unroll
        for (int i = 0; i < ITERS; i++) {
            int u = tid + (i << 8);
            uint32_t d;
            const __half* src;
            if (u < AUNITS) {
                int t = (APL == 2) ? (u >> 9) : 0;
                int r2 = (u >> 2) & 127, c = u & 3;
                src = (t ? A + aPlane : A) + (size_t)(m0 + r2) * K + kk + c * 8;
                d = st + t * 8192 + r2 * 64 + ((c ^ ((r2 >> 1) & 3)) << 4);
            } else {
                int v = u - AUNITS;
                if (BN == 128) {
                    int r2 = (v >> 2) & 127, c = v & 3;
                    src = B + (size_t)(n0 + r2) * K + kk + c * 8;
                    d = st + BBASE + r2 * 64 + ((c ^ ((r2 >> 1) & 3)) << 4);
                } else {
                    int t2 = v >> 8, r2 = (v >> 2) & 63, c = v & 3;
                    src = (t2 ? B + bPlane : B) + (size_t)(n0 + r2) * K + kk + c * 8;
                    d = st + BBASE + t2 * 4096 + r2 * 64 + ((c ^ ((r2 >> 1) & 3)) << 4);
                }
            }
            cpAsync16(d, src);
        }
        asm volatile("cp.async.commit_group;" ::: "memory");
    };

    loadStage(0, kStart);
    if (kPerSplit > 1) loadStage(1, kStart + 1);

    for (int ch = 0; ch < kPerSplit; ch++) {
        if (ch + 1 < kPerSplit)
            asm volatile("cp.async.wait_group 1;" ::: "memory");
        else
            asm volatile("cp.async.wait_group 0;" ::: "memory");
        __syncthreads();
        if (ch + 2 < kPerSplit) loadStage((ch + 2) % 3, kStart + ch + 2);

        const uint32_t st = sb + (ch % 3) * STAGE;
#pragma unroll
        for (int ks = 0; ks < 2; ks++) {
            uint32_t ah[4][4], al[4][4];
#pragma unroll
            for (int mt = 0; mt < 4; mt++) {
                int r2 = wm * 64 + mt * 16 + (lane & 15);
                int c = ks * 2 + (lane >> 4);
                uint32_t ad = st + r2 * 64 + ((c ^ ((r2 >> 1) & 3)) << 4);
                ldsm4(ah[mt], ad);
                if (NPROD >= 2) ldsm4(al[mt], ad + 8192);
            }
#pragma unroll
            for (int pair = 0; pair < NT / 2; pair++) {
                int rb = wn * WNW + pair * 16 + ((lane >> 4) << 3) + (lane & 7);
                int cb = ks * 2 + ((lane >> 3) & 1);
                uint32_t bd = st + BBASE + rb * 64 + ((cb ^ ((rb >> 1) & 3)) << 4);
                uint32_t bh[4];
                ldsm4(bh, bd);
#pragma unroll
                for (int mt = 0; mt < 4; mt++) {
                    mmaF16(acc[mt][2 * pair], ah[mt], bh);
                    mmaF16(acc[mt][2 * pair + 1], ah[mt], bh + 2);
                }
                if (NPROD >= 2) {
#pragma unroll
                    for (int mt = 0; mt < 4; mt++) {
                        mmaF16(acc[mt][2 * pair], al[mt], bh);
                        mmaF16(acc[mt][2 * pair + 1], al[mt], bh + 2);
                    }
                }
                if (NPROD == 3) {
                    uint32_t bl[4];
                    ldsm4(bl, bd + BN * 64);
#pragma unroll
                    for (int mt = 0; mt < 4; mt++) {
                        mmaF16(acc[mt][2 * pair], ah[mt], bl);
                        mmaF16(acc[mt][2 * pair + 1], ah[mt], bl + 2);
                    }
                }
            }
        }
        __syncthreads();
    }

    // ---- epilogue ----
    if (EPI <= 1) {
        float* Cp = Cf + (EPI == 1 ? (size_t)blockIdx.z * planeOrPart : 0);
#pragma unroll
        for (int nt = 0; nt < NT; nt++) {
            int c0 = n0 + wn * WNW + nt * 8 + 2 * t4;
            float b0 = 0.0f, b1 = 0.0f;
            if (EPI == 0 && bias) { b0 = bias[c0]; b1 = bias[c0 + 1]; }
#pragma unroll
            for (int mt = 0; mt < 4; mt++) {
                int r1 = m0 + wm * 64 + mt * 16 + g;
                *(float2*)&Cp[(size_t)r1 * 1024 + c0] =
                    make_float2(acc[mt][nt][0] + b0, acc[mt][nt][1] + b1);
                *(float2*)&Cp[(size_t)(r1 + 8) * 1024 + c0] =
                    make_float2(acc[mt][nt][2] + b0, acc[mt][nt][3] + b1);
            }
        }
    } else {
        const float rs = (EPI == 3) ? (1.0f / 32.0f) : 1.0f;
#pragma unroll
        for (int mt = 0; mt < 4; mt++) {
            int r1 = m0 + wm * 64 + mt * 16 + g;
            int r2 = r1 + 8;
            float bv1 = 0, w21 = 0, bv2 = 0, w22 = 0;
            if (EPI == 3) {
                bv1 = bvV[r1]; w21 = wV[r1] + 8192.0f * bv1;
                bv2 = bvV[r2]; w22 = wV[r2] + 8192.0f * bv2;
            }
#pragma unroll
            for (int nt = 0; nt < NT; nt++) {
                int c0 = n0 + wn * WNW + nt * 8 + 2 * t4;
                float pa = 0, pb = 0, qa = 0, qb = 0;
                if (EPI == 3) { pa = p1V[c0]; pb = p1V[c0 + 1]; qa = p2V[c0]; qb = p2V[c0 + 1]; }
                float v1a = (acc[mt][nt][0] + bv1 * pa + w21 * qa) * rs;
                float v1b = (acc[mt][nt][1] + bv1 * pb + w21 * qb) * rs;
                float v2a = (acc[mt][nt][2] + bv2 * pa + w22 * qa) * rs;
                float v2b = (acc[mt][nt][3] + bv2 * pb + w22 * qb) * rs;
                size_t o1 = (size_t)r1 * 1024 + c0;
                size_t o2 = (size_t)r2 * 1024 + c0;
                __half h;
                h = __float2half_rn(v1a); Ch[o1] = h;
                Ch[planeOrPart + o1] = __float2half_rn(v1a - __half2float(h));
                h = __float2half_rn(v1b); Ch[o1 + 1] = h;
                Ch[planeOrPart + o1 + 1] = __float2half_rn(v1b - __half2float(h));
                h = __float2half_rn(v2a); Ch[o2] = h;
                Ch[planeOrPart + o2] = __float2half_rn(v2a - __half2float(h));
                h = __float2half_rn(v2b); Ch[o2 + 1] = h;
                Ch[planeOrPart + o2 + 1] = __float2half_rn(v2b - __half2float(h));
            }
        }
    }
}

// ---------------- packs ----------------
// merged weight pack: z=0 Wv (no trans), z=1 Wq^T, z=2 Wk^T. grid (16, 8, 3)
__global__ void packW(const float* __restrict__ Wv, const float* __restrict__ Wq,
                      const float* __restrict__ Wk, __half* __restrict__ Wvp,
                      __half* __restrict__ WqTp, __half* __restrict__ WkTp) {
    __shared__ float tile[64][129];
    const int z = blockIdx.z;
    const float* src = (z == 0) ? Wv : ((z == 1) ? Wq : Wk);
    __half* dst = (z == 0) ? Wvp : ((z == 1) ? WqTp : WkTp);
    const bool trans = (z != 0);
    const int k0 = blockIdx.x * 64, m0 = blockIdx.y * 128;
    const int tid = threadIdx.x;
    if (trans) {
        for (int idx = tid; idx < 64 * 128; idx += 256) {
            int k = idx >> 7, m = idx & 127;
            tile[k][m] = src[(size_t)(k0 + k) * HDIM + m0 + m];
        }
        __syncthreads();
    }
    for (int idx = tid; idx < 128 * 16; idx += 256) {
        int m = idx >> 4, q = idx & 15;
        float v[4];
        if (trans) {
#pragma unroll
            for (int i = 0; i < 4; i++) v[i] = tile[q * 4 + i][m];
        } else {
            float4 f = *(const float4*)(src + (size_t)(m0 + m) * HDIM + k0 + q * 4);
            v[0] = f.x; v[1] = f.y; v[2] = f.z; v[3] = f.w;
        }
        uint2 hiw, low;
        split4(v, hiw, low);
        size_t off = (size_t)(m0 + m) * 1024 + k0 + q * 4;
        *(uint2*)(dst + off) = hiw;
        *(uint2*)(dst + PH + off) = low;
    }
}

// fused x pack: xp[n][h], xTp[h][n] fp16 hi/lo planes + column-sum into s. grid (16, 64)
__global__ void packXfused(const float* __restrict__ x, __half* __restrict__ xp,
                           __half* __restrict__ xTp, float* __restrict__ s) {
    __shared__ float tile[64][132];
    const int h0 = blockIdx.x * 64, n0 = blockIdx.y * 128;
    const int tid = threadIdx.x;
    for (int idx = tid; idx < 128 * 64; idx += 256) {
        int n = idx >> 6, h = idx & 63;
        tile[h][n] = x[(size_t)(n0 + n) * HDIM + h0 + h];
    }
    __syncthreads();
    if (tid < 64) {
        float a = 0.0f;
#pragma unroll 8
        for (int n = 0; n < 128; n++) a += tile[tid][n];
        atomicAdd(&s[h0 + tid], a);
    }
    for (int idx = tid; idx < 128 * 16; idx += 256) {
        int m = idx >> 4, q = idx & 15;
        float v[4];
#pragma unroll
        for (int i = 0; i < 4; i++) v[i] = tile[q * 4 + i][m];
        uint2 hiw, low;
        split4(v, hiw, low);
        size_t off = (size_t)(n0 + m) * 1024 + h0 + q * 4;
        *(uint2*)(xp + off) = hiw;
        *(uint2*)(xp + PX + off) = low;
    }
    for (int idx = tid; idx < 64 * 32; idx += 256) {
        int h = idx >> 5, s4 = idx & 31;
        float v[4];
#pragma unroll
        for (int i = 0; i < 4; i++) v[i] = tile[h][s4 * 4 + i];
        uint2 hiw, low;
        split4(v, hiw, low);
        size_t off = (size_t)(h0 + h) * 8192 + n0 + s4 * 4;
        *(uint2*)(xTp + off) = hiw;
        *(uint2*)(xTp + PX + off) = low;
    }
}

// G pack with symmetric mirror. grid (16, 8)
__global__ void packG(const float* __restrict__ part, __half* __restrict__ dst) {
    __shared__ float tile[64][129];
    const int k0 = blockIdx.x * 64, m0 = blockIdx.y * 128;
    const int mt = m0 >> 7, kt = k0 >> 7;
    const int tid = threadIdx.x;
    const bool mirror = (mt > kt);
    if (mirror) {
        for (int idx = tid; idx < 64 * 128; idx += 256) {
            int k = idx >> 7, m = idx & 127;
            const float* p = part + (size_t)(k0 + k) * 1024 + m0 + m;
            tile[k][m] = p[0] + p[PH] + p[2 * PH] + p[3 * PH];
        }
        __syncthreads();
    }
    for (int idx = tid; idx < 128 * 16; idx += 256) {
        int m = idx >> 4, q = idx & 15;
        float v[4];
        if (mirror) {
#pragma unroll
            for (int i = 0; i < 4; i++) v[i] = tile[q * 4 + i][m];
        } else {
            const float* p = part + (size_t)(m0 + m) * 1024 + k0 + q * 4;
            float4 a = *(const float4*)p;
            float4 b = *(const float4*)(p + PH);
            float4 c = *(const float4*)(p + 2 * PH);
            float4 e = *(const float4*)(p + 3 * PH);
            v[0] = a.x + b.x + c.x + e.x;
            v[1] = a.y + b.y + c.y + e.y;
            v[2] = a.z + b.z + c.z + e.z;
            v[3] = a.w + b.w + c.w + e.w;
        }
        uint2 hiw, low;
        split4(v, hiw, low);
        size_t off = (size_t)(m0 + m) * 1024 + k0 + q * 4;
        *(uint2*)(dst + off) = hiw;
        *(uint2*)(dst + PH + off) = low;
    }
}

// ---------------- vector kernels ----------------
__global__ void zeroVec(float* a, float* b, float* c, float* e, float* f2, float* g2) {
    int i = blockIdx.x * 256 + threadIdx.x;
    if (i < 1024) {
        a[i] = 0.0f; b[i] = 0.0f; c[i] = 0.0f;
        e[i] = 0.0f; f2[i] = 0.0f; g2[i] = 0.0f;
    }
}
// y=0: u = Wk s ; y=1: w = Wv s.  grid (128, 2) -> 1024 warps per y
__global__ void matvecK2(const float* __restrict__ Wk, const float* __restrict__ Wv,
                         const float* __restrict__ s, float* __restrict__ u,
                         float* __restrict__ w) {
    const float* W = blockIdx.y ? Wv : Wk;
    float* out = blockIdx.y ? w : u;
    int gw = (blockIdx.x * 256 + threadIdx.x) >> 5;
    int lane = threadIdx.x & 31;
    if (gw < HDIM) {
        const float* wrow = W + (size_t)gw * HDIM;
        float acc = 0.0f;
        for (int j = lane; j < HDIM; j += 32) acc += wrow[j] * s[j];
#pragma unroll
        for (int o = 16; o > 0; o >>= 1) acc += __shfl_xor_sync(0xFFFFFFFFu, acc, o);
        if (lane == 0) out[gw] = acc;
    }
}
// z=0: z1 += Wk^T bq ; z=1: p2 += Wq^T bk.  grid (4, 8, 2)
__global__ void matvecT2(const float* __restrict__ Wk, const float* __restrict__ Wq,
                         const float* __restrict__ bq, const float* __restrict__ bk,
                         float* __restrict__ z1, float* __restrict__ p2) {
    __shared__ float vs[128];
    const float* W = blockIdx.z ? Wq : Wk;
    const float* v = blockIdx.z ? bk : bq;
    float* out = blockIdx.z ? p2 : z1;
    int c = blockIdx.x * 256 + threadIdx.x;
    int i0 = blockIdx.y * 128;
    if (threadIdx.x < 128) vs[threadIdx.x] = v[i0 + threadIdx.x];
    __syncthreads();
    float acc = 0.0f;
#pragma unroll 8
    for (int i = 0; i < 128; i++) acc += W[(size_t)(i0 + i) * HDIM + c] * vs[i];
    atomicAdd(&out[c], acc);
}
__global__ void matvecT(const float* __restrict__ W, const float* __restrict__ v,
                        float* __restrict__ out) {
    __shared__ float vs[128];
    int c = blockIdx.x * 256 + threadIdx.x;
    int i0 = blockIdx.y * 128;
    if (threadIdx.x < 128) vs[threadIdx.x] = v[i0 + threadIdx.x];
    __syncthreads();
    float acc = 0.0f;
#pragma unroll 8
    for (int i = 0; i < 128; i++) acc += W[(size_t)(i0 + i) * HDIM + c] * vs[i];
    atomicAdd(&out[c], acc);
}
__global__ void dotsKernel(const float* __restrict__ u, const float* __restrict__ bq,
                           const float* __restrict__ bk, float* __restrict__ d) {
    __shared__ float s1[256], s2[256];
    int t = threadIdx.x;
    float a = 0, b = 0;
    for (int i = t; i < 1024; i += 256) { a += u[i] * bq[i]; b += bk[i] * bq[i]; }
    s1[t] = a; s2[t] = b;
    __syncthreads();
    for (int o = 128; o > 0; o >>= 1) {
        if (t < o) { s1[t] += s1[t + o]; s2[t] += s2[t + o]; }
        __syncthreads();
    }
    if (t == 0) { d[0] = s1[0]; d[1] = s2[0]; }
}
// z2[i] = dot(G[i,:], z1) from fp16 hi+lo planes
__global__ void matvecH(const __half* __restrict__ Gp, const float* __restrict__ z1,
                        float* __restrict__ z2) {
    int gw = (blockIdx.x * blockDim.x + threadIdx.x) >> 5;
    int lane = threadIdx.x & 31;
    if (gw < HDIM) {
        const __half* row = Gp + (size_t)gw * 1024;
        float acc = 0.0f;
        for (int j = lane; j < HDIM; j += 32)
            acc += (__half2float(row[j]) + __half2float(row[PH + j])) * z1[j];
#pragma unroll
        for (int o = 16; o > 0; o >>= 1) acc += __shfl_xor_sync(0xFFFFFFFFu, acc, o);
        if (lane == 0) z2[gw] = acc;
    }
}
__global__ void rFinal(const float* __restrict__ Wv, const float* __restrict__ z2,
                       const float* __restrict__ d, const float* __restrict__ bv,
                       const float* __restrict__ w, float* __restrict__ r) {
    int gw = (blockIdx.x * blockDim.x + threadIdx.x) >> 5;
    int lane = threadIdx.x & 31;
    if (gw < HDIM) {
        const float* wrow = Wv + (size_t)gw * HDIM;
        float acc = 0.0f;
        for (int j = lane; j < HDIM; j += 32) acc += wrow[j] * z2[j];
#pragma unroll
        for (int o = 16; o > 0; o >>= 1) acc += __shfl_xor_sync(0xFFFFFFFFu, acc, o);
        if (lane == 0)
            r[gw] = (acc + d[0] * bv[gw] + d[1] * (w[gw] + 8192.0f * bv[gw])) * (1.0f / 32.0f);
    }
}

// ---------------- launch ----------------
extern "C" void kernel_launch(void* const* d_in, const int* in_sizes, int n_in,
                              void* d_out, int out_size) {
    const float* x  = (const float*)d_in[0];
    const float* Wq = (const float*)d_in[1];
    const float* bq = (const float*)d_in[2];
    const float* Wk = (const float*)d_in[3];
    const float* bk = (const float*)d_in[4];
    const float* Wv = (const float*)d_in[5];
    const float* bv = (const float*)d_in[6];
    float* out = (float*)d_out;

    __half *xTp, *xp, *Ptp, *Wvp, *WqTp, *WkTp, *Gp, *A1tp, *Ep;
    float *part, *s, *u, *w, *z1, *z2, *p1, *p2, *r, *d;
    cudaGetSymbolAddress((void**)&xTp, g_xTp);
    cudaGetSymbolAddress((void**)&xp, g_xp);
    cudaGetSymbolAddress((void**)&Ptp, g_Ptp);
    cudaGetSymbolAddress((void**)&Wvp, g_Wvp);
    cudaGetSymbolAddress((void**)&WqTp, g_WqTp);
    cudaGetSymbolAddress((void**)&WkTp, g_WkTp);
    cudaGetSymbolAddress((void**)&Gp, g_Gp);
    cudaGetSymbolAddress((void**)&A1tp, g_A1tp);
    cudaGetSymbolAddress((void**)&Ep, g_Ep);
    cudaGetSymbolAddress((void**)&part, g_part);
    cudaGetSymbolAddress((void**)&s, g_s);
    cudaGetSymbolAddress((void**)&u, g_u);
    cudaGetSymbolAddress((void**)&w, g_w);
    cudaGetSymbolAddress((void**)&z1, g_z1);
    cudaGetSymbolAddress((void**)&z2, g_z2);
    cudaGetSymbolAddress((void**)&p1, g_p1);
    cudaGetSymbolAddress((void**)&p2, g_p2);
    cudaGetSymbolAddress((void**)&r, g_r);
    cudaGetSymbolAddress((void**)&d, g_d);

    auto GemmG   = gemmTC<2, 128, 1, 1>;   // symmetric triangle, split-K partials
    auto GemmOut = gemmTC<1, 128, 0, 0>;   // 1-product, fp32 + bias row
    auto GemmSm  = gemmTC<3, 64, 2, 0>;    // fp16 planes out
    auto GemmPt  = gemmTC<3, 64, 3, 0>;    // fp16 planes + rank-2 + 1/32
    cudaFuncSetAttribute(GemmG, cudaFuncAttributeMaxDynamicSharedMemorySize, GEMM_SMEM);
    cudaFuncSetAttribute(GemmOut, cudaFuncAttributeMaxDynamicSharedMemorySize, GEMM_SMEM);
    cudaFuncSetAttribute(GemmSm, cudaFuncAttributeMaxDynamicSharedMemorySize, GEMM_SMEM);
    cudaFuncSetAttribute(GemmPt, cudaFuncAttributeMaxDynamicSharedMemorySize, GEMM_SMEM);

    // vectors init + packs (zero u,w too: partial-write safety)
    zeroVec<<<4, 256>>>(s, z1, p1, p2, u, w);
    packXfused<<<dim3(16, 64), 256>>>(x, xp, xTp, s);
    packW<<<dim3(16, 8, 3), 256>>>(Wv, Wq, Wk, Wvp, WqTp, WkTp);

    // vector chain  (grid FIXED: 128 x-blocks -> 1024 warps per matrix)
    matvecK2<<<dim3(128, 2), 256>>>(Wk, Wv, s, u, w);
    matvecT2<<<dim3(4, 8, 2), 256>>>(Wk, Wq, bq, bk, z1, p2);
    matvecT<<<dim3(4, 8), 256>>>(Wq, u, p1);
    dotsKernel<<<1, 256>>>(u, bq, bk, d);

    // E = op(WqT, WkT)
    GemmSm<<<dim3(16, 8, 1), 256, GEMM_SMEM>>>(WqTp, WkTp, nullptr, Ep, 1024, PH, PH, 32,
                                               nullptr, PH, nullptr, nullptr, nullptr, nullptr);
    // G = op(xT, xT): 36 triangle tiles x split-K 4
    GemmG<<<dim3(36, 1, 4), 256, GEMM_SMEM>>>(xTp, xTp, part, nullptr, 8192, PX, PX,
                                              64, nullptr, PH, nullptr, nullptr, nullptr, nullptr);
    packG<<<dim3(16, 8), 256>>>(part, Gp);
    matvecH<<<128, 256>>>(Gp, z1, z2);

    // A1t = op(Wv, G)
    GemmSm<<<dim3(16, 8, 1), 256, GEMM_SMEM>>>(Wvp, Gp, nullptr, A1tp, 1024, PH, PH, 32,
                                               nullptr, PH, nullptr, nullptr, nullptr, nullptr);
    // Pt = op(A1t, E) + rank2, /32
    GemmPt<<<dim3(16, 8, 1), 256, GEMM_SMEM>>>(A1tp, Ep, nullptr, Ptp, 1024, PH, PH, 32,
                                               nullptr, PH, bv, w, p1, p2);
    // r
    rFinal<<<128, 256>>>(Wv, z2, d, bv, w, r);
    // out = op(x, Pt) + r   (1-product: hi planes only)
    GemmOut<<<dim3(8, 64, 1), 256, GEMM_SMEM>>>(xp, Ptp, out, nullptr, 1024, PX, PH,
                                                32, r, 0, nullptr, nullptr, nullptr, nullptr);
}